// round 4
// baseline (speedup 1.0000x reference)
#include <cuda_runtime.h>
#include <math.h>
#include <stdint.h>

// Problem constants
#define BB 2
#define TT 2048
#define DM 2048
#define NH 16
#define HD 128
#define NKV 4
#define NREP 4
#define HALF 64
#define MTOT (BB*TT)      // 4096
#define QN (NH*HD)        // 2048
#define KN (NKV*HD)       // 512

// Scratch (device globals: no allocations allowed)
__device__ float g_q[MTOT * QN];      // (b,t,h,d)  32 MB
__device__ float g_k[MTOT * KN];      // (b,t,kv,d)  8 MB
__device__ float g_v[MTOT * KN];      //             8 MB
__device__ float g_attn[MTOT * QN];   // (b,t,h,d)  32 MB

// ---------------------------------------------------------------------------
// Tiled fp32 GEMM: C[M,N] = A[M,K] @ B[K,N], all row-major.
// 128x128 tile, TK=16, 256 threads, 8x8 per-thread fragment.
// M,N,K all divisible by tile sizes (4096 / {2048,512} / 2048).
// ---------------------------------------------------------------------------
__global__ __launch_bounds__(256) void gemm128(
    const float* __restrict__ A, const float* __restrict__ Bm,
    float* __restrict__ C, int M, int N, int K)
{
    __shared__ float As[16][128];   // transposed: As[k][m]
    __shared__ float Bs[16][128];   // Bs[k][n]

    const int tid = threadIdx.x;
    const int tx = tid & 15;        // n dim
    const int ty = tid >> 4;        // m dim
    const int m0 = blockIdx.y * 128;
    const int n0 = blockIdx.x * 128;

    float acc[8][8];
#pragma unroll
    for (int i = 0; i < 8; i++)
#pragma unroll
        for (int j = 0; j < 8; j++) acc[i][j] = 0.0f;

    for (int k0 = 0; k0 < K; k0 += 16) {
        // Load A tile 128x16 (512 float4)
#pragma unroll
        for (int i = 0; i < 2; i++) {
            int idx = tid + i * 256;            // 0..511
            int r = idx >> 2;                   // 0..127
            int c4 = idx & 3;                   // 0..3
            float4 va = *(const float4*)&A[(size_t)(m0 + r) * K + k0 + c4 * 4];
            As[c4 * 4 + 0][r] = va.x;
            As[c4 * 4 + 1][r] = va.y;
            As[c4 * 4 + 2][r] = va.z;
            As[c4 * 4 + 3][r] = va.w;
        }
        // Load B tile 16x128 (512 float4)
#pragma unroll
        for (int i = 0; i < 2; i++) {
            int idx = tid + i * 256;
            int r = idx >> 5;                   // 0..15
            int c4 = idx & 31;                  // 0..31
            *(float4*)&Bs[r][c4 * 4] =
                *(const float4*)&Bm[(size_t)(k0 + r) * N + n0 + c4 * 4];
        }
        __syncthreads();

#pragma unroll
        for (int kk = 0; kk < 16; kk++) {
            float4 a0 = *(const float4*)&As[kk][ty * 8];
            float4 a1 = *(const float4*)&As[kk][ty * 8 + 4];
            float4 b0 = *(const float4*)&Bs[kk][tx * 8];
            float4 b1 = *(const float4*)&Bs[kk][tx * 8 + 4];
            float a[8] = {a0.x, a0.y, a0.z, a0.w, a1.x, a1.y, a1.z, a1.w};
            float b[8] = {b0.x, b0.y, b0.z, b0.w, b1.x, b1.y, b1.z, b1.w};
#pragma unroll
            for (int i = 0; i < 8; i++)
#pragma unroll
                for (int j = 0; j < 8; j++)
                    acc[i][j] += a[i] * b[j];
        }
        __syncthreads();
    }

#pragma unroll
    for (int i = 0; i < 8; i++) {
        size_t row = (size_t)(m0 + ty * 8 + i) * N + n0 + tx * 8;
        float4 r0 = {acc[i][0], acc[i][1], acc[i][2], acc[i][3]};
        float4 r1 = {acc[i][4], acc[i][5], acc[i][6], acc[i][7]};
        *(float4*)&C[row]     = r0;
        *(float4*)&C[row + 4] = r1;
    }
}

// ---------------------------------------------------------------------------
// RoPE in-place on (B, T, heads, HD) tensor.
// ---------------------------------------------------------------------------
__global__ void rope_kernel(float* __restrict__ q,
                            const float* __restrict__ cosp,
                            const float* __restrict__ sinp,
                            int heads)
{
    int idx = blockIdx.x * blockDim.x + threadIdx.x;
    int total = BB * TT * heads * HALF;
    if (idx >= total) return;
    int i = idx % HALF;
    int h = (idx / HALF) % heads;
    int t = (idx / (HALF * heads)) % TT;
    int b = idx / (HALF * heads * TT);
    float c = cosp[t * HALF + i];
    float s = sinp[t * HALF + i];
    float* p = q + ((((size_t)b * TT + t) * heads + h) * HD);
    float x1 = p[i];
    float x2 = p[i + HALF];
    p[i]        = x1 * c - x2 * s;
    p[i + HALF] = x2 * c + x1 * s;
}

// ---------------------------------------------------------------------------
// Causal GQA flash attention, fp32.
// Q/K/V layouts: Q (b,t,h,d) stride NH*HD; K,V (b,t,kv,d) stride NKV*HD.
// Tile: BM=64 q rows x BN=64 kv cols, 256 threads (tx 0..15 cols/d, ty 0..15 rows).
// Score frag 4x4 per thread; O frag 4 rows x 8 d per thread.
// Smem: Qt[128][68] k-major (prescaled), Kt[128][68] k-major, Vs[64][128], Ps[64][68].
// ---------------------------------------------------------------------------
#define Bb 64
#define BNN 64
#define APAD 4
#define ATT_SMEM_FLOATS (128*(Bb+APAD) + 128*(BNN+APAD) + BNN*128 + Bb*(BNN+APAD))
#define ATT_SMEM_BYTES  (ATT_SMEM_FLOATS * 4)

__global__ __launch_bounds__(256) void attn_kernel(
    const float* __restrict__ Q, const float* __restrict__ Kc,
    const float* __restrict__ Vc, float* __restrict__ Oc)
{
    extern __shared__ float smf[];
    float* Qt = smf;                              // [128][BM+4]
    float* Kt = Qt + 128 * (Bb + APAD);           // [128][BN+4]
    float* Vs = Kt + 128 * (BNN + APAD);          // [BN][128]
    float* Ps = Vs + BNN * 128;                   // [BM][BN+4]

    const int tid = threadIdx.x;
    const int tx = tid & 15;
    const int ty = tid >> 4;
    // Reverse qt order: longest CTAs first (better tail with 1 CTA/SM occupancy)
    const int qt = (gridDim.x - 1) - blockIdx.x;
    const int h  = blockIdx.y;
    const int b  = blockIdx.z;
    const int kvh = h >> 2;                        // h / NREP
    const int qi0 = qt * Bb;
    const float scale = 0.08838834764831845f;      // 1/sqrt(128)

    // ---- load Q tile (transposed, pre-scaled) ----
    const float* qbase = Q + (((size_t)b * TT + qi0) * NH + h) * HD;
#pragma unroll
    for (int i = 0; i < 8; i++) {
        int idx = tid + i * 256;       // 0..2047
        int r  = idx >> 5;             // 0..63
        int d4 = idx & 31;             // 0..31
        float4 vq = *(const float4*)&qbase[(size_t)r * QN + d4 * 4];
        Qt[(d4 * 4 + 0) * (Bb + APAD) + r] = vq.x * scale;
        Qt[(d4 * 4 + 1) * (Bb + APAD) + r] = vq.y * scale;
        Qt[(d4 * 4 + 2) * (Bb + APAD) + r] = vq.z * scale;
        Qt[(d4 * 4 + 3) * (Bb + APAD) + r] = vq.w * scale;
    }

    float m_i[4], l_i[4], o[4][8];
#pragma unroll
    for (int ii = 0; ii < 4; ii++) {
        m_i[ii] = -1e30f;
        l_i[ii] = 0.0f;
#pragma unroll
        for (int dd = 0; dd < 8; dd++) o[ii][dd] = 0.0f;
    }

    const int ntiles = qi0 / BNN + 1;
    for (int kt = 0; kt < ntiles; kt++) {
        const int kj0 = kt * BNN;
        __syncthreads();   // protect Qt (first iter) / Kt,Vs from prior iter readers

        // ---- load K (transposed) and V tiles ----
        const float* kbase = Kc + (((size_t)b * TT + kj0) * NKV + kvh) * HD;
        const float* vbase = Vc + (((size_t)b * TT + kj0) * NKV + kvh) * HD;
#pragma unroll
        for (int i = 0; i < 8; i++) {
            int idx = tid + i * 256;
            int r  = idx >> 5;
            int d4 = idx & 31;
            float4 vk = *(const float4*)&kbase[(size_t)r * KN + d4 * 4];
            Kt[(d4 * 4 + 0) * (BNN + APAD) + r] = vk.x;
            Kt[(d4 * 4 + 1) * (BNN + APAD) + r] = vk.y;
            Kt[(d4 * 4 + 2) * (BNN + APAD) + r] = vk.z;
            Kt[(d4 * 4 + 3) * (BNN + APAD) + r] = vk.w;
            float4 vv = *(const float4*)&vbase[(size_t)r * KN + d4 * 4];
            *(float4*)&Vs[r * 128 + d4 * 4] = vv;
        }
        __syncthreads();

        // ---- S = Q K^T  (4x4 frag) ----
        float acc[4][4];
#pragma unroll
        for (int ii = 0; ii < 4; ii++)
#pragma unroll
            for (int jj = 0; jj < 4; jj++) acc[ii][jj] = 0.0f;

#pragma unroll 8
        for (int kk = 0; kk < HD; kk++) {
            float4 a = *(const float4*)&Qt[kk * (Bb + APAD) + ty * 4];
            float4 bb = *(const float4*)&Kt[kk * (BNN + APAD) + tx * 4];
            float av[4] = {a.x, a.y, a.z, a.w};
            float bv[4] = {bb.x, bb.y, bb.z, bb.w};
#pragma unroll
            for (int ii = 0; ii < 4; ii++)
#pragma unroll
                for (int jj = 0; jj < 4; jj++)
                    acc[ii][jj] += av[ii] * bv[jj];
        }

        // ---- causal mask (only diagonal tile needs it) ----
        if (kt == ntiles - 1) {
#pragma unroll
            for (int ii = 0; ii < 4; ii++) {
                int qi = qi0 + ty * 4 + ii;
#pragma unroll
                for (int jj = 0; jj < 4; jj++) {
                    int kj = kj0 + tx * 4 + jj;
                    if (kj > qi) acc[ii][jj] = -1e30f;
                }
            }
        }

        // ---- online softmax (reduce across 16 tx lanes via shfl) ----
#pragma unroll
        for (int ii = 0; ii < 4; ii++) {
            float tmax = fmaxf(fmaxf(acc[ii][0], acc[ii][1]),
                               fmaxf(acc[ii][2], acc[ii][3]));
#pragma unroll
            for (int off = 1; off < 16; off <<= 1)
                tmax = fmaxf(tmax, __shfl_xor_sync(0xffffffffu, tmax, off));
            float mnew = fmaxf(m_i[ii], tmax);
            float corr = __expf(m_i[ii] - mnew);
            float p0 = __expf(acc[ii][0] - mnew);
            float p1 = __expf(acc[ii][1] - mnew);
            float p2 = __expf(acc[ii][2] - mnew);
            float p3 = __expf(acc[ii][3] - mnew);
            float rsum = (p0 + p1) + (p2 + p3);
#pragma unroll
            for (int off = 1; off < 16; off <<= 1)
                rsum += __shfl_xor_sync(0xffffffffu, rsum, off);
            l_i[ii] = l_i[ii] * corr + rsum;
            m_i[ii] = mnew;
#pragma unroll
            for (int dd = 0; dd < 8; dd++) o[ii][dd] *= corr;
            float4 pv = {p0, p1, p2, p3};
            *(float4*)&Ps[(ty * 4 + ii) * (BNN + APAD) + tx * 4] = pv;
        }
        __syncwarp();   // Ps produced & consumed within the same warp

        // ---- O += P @ V  (4 rows x 8 d per thread) ----
#pragma unroll 4
        for (int j = 0; j < BNN; j++) {
            float4 v0 = *(const float4*)&Vs[j * 128 + tx * 8];
            float4 v1 = *(const float4*)&Vs[j * 128 + tx * 8 + 4];
#pragma unroll
            for (int ii = 0; ii < 4; ii++) {
                float p = Ps[(ty * 4 + ii) * (BNN + APAD) + j];
                o[ii][0] += p * v0.x;  o[ii][1] += p * v0.y;
                o[ii][2] += p * v0.z;  o[ii][3] += p * v0.w;
                o[ii][4] += p * v1.x;  o[ii][5] += p * v1.y;
                o[ii][6] += p * v1.z;  o[ii][7] += p * v1.w;
            }
        }
    }

    // ---- epilogue: normalize & store (b,t,h,d) ----
    float* obase = Oc + (((size_t)b * TT + qi0) * NH + h) * HD;
#pragma unroll
    for (int ii = 0; ii < 4; ii++) {
        float inv = 1.0f / l_i[ii];
        int r = ty * 4 + ii;
        float4 r0 = {o[ii][0] * inv, o[ii][1] * inv, o[ii][2] * inv, o[ii][3] * inv};
        float4 r1 = {o[ii][4] * inv, o[ii][5] * inv, o[ii][6] * inv, o[ii][7] * inv};
        *(float4*)&obase[(size_t)r * QN + tx * 8]     = r0;
        *(float4*)&obase[(size_t)r * QN + tx * 8 + 4] = r1;
    }
}

// ---------------------------------------------------------------------------
// Launch
// ---------------------------------------------------------------------------
extern "C" void kernel_launch(void* const* d_in, const int* in_sizes, int n_in,
                              void* d_out, int out_size)
{
    const float* x    = (const float*)d_in[0];
    const float* wq   = (const float*)d_in[1];
    const float* wk   = (const float*)d_in[2];
    const float* wv   = (const float*)d_in[3];
    const float* wo   = (const float*)d_in[4];
    const float* cosp = (const float*)d_in[5];
    const float* sinp = (const float*)d_in[6];
    float* out = (float*)d_out;

    float *qp, *kp, *vp, *ap;
    cudaGetSymbolAddress((void**)&qp, g_q);
    cudaGetSymbolAddress((void**)&kp, g_k);
    cudaGetSymbolAddress((void**)&vp, g_v);
    cudaGetSymbolAddress((void**)&ap, g_attn);

    cudaFuncSetAttribute(attn_kernel,
                         cudaFuncAttributeMaxDynamicSharedMemorySize,
                         ATT_SMEM_BYTES);

    // QKV projections
    gemm128<<<dim3(QN / 128, MTOT / 128), 256>>>(x, wq, qp, MTOT, QN, DM);
    gemm128<<<dim3(KN / 128, MTOT / 128), 256>>>(x, wk, kp, MTOT, KN, DM);
    gemm128<<<dim3(KN / 128, MTOT / 128), 256>>>(x, wv, vp, MTOT, KN, DM);

    // RoPE (in-place)
    {
        int tq = BB * TT * NH * HALF;
        rope_kernel<<<(tq + 255) / 256, 256>>>(qp, cosp, sinp, NH);
        int tk = BB * TT * NKV * HALF;
        rope_kernel<<<(tk + 255) / 256, 256>>>(kp, cosp, sinp, NKV);
    }

    // Flash attention
    attn_kernel<<<dim3(TT / Bb, NH, BB), 256, ATT_SMEM_BYTES>>>(qp, kp, vp, ap);

    // Output projection
    gemm128<<<dim3(QN / 128, MTOT / 128), 256>>>(ap, wo, out, MTOT, QN, DM);
}

// round 5
// speedup vs baseline: 1.0017x; 1.0017x over previous
#include <cuda_runtime.h>
#include <math.h>
#include <stdint.h>

// Problem constants
#define BB 2
#define TT 2048
#define DM 2048
#define NH 16
#define HD 128
#define NKV 4
#define NREP 4
#define HALF 64
#define MTOT (BB*TT)      // 4096
#define QN (NH*HD)        // 2048
#define KN (NKV*HD)       // 512

// Scratch (device globals: no allocations allowed)
__device__ float g_q[MTOT * QN];      // (b,t,h,d)  32 MB
__device__ float g_k[MTOT * KN];      // (b,t,kv,d)  8 MB
__device__ float g_v[MTOT * KN];      //             8 MB
__device__ float g_attn[MTOT * QN];   // (b,t,h,d)  32 MB

// ---------------------------------------------------------------------------
// Tiled fp32 GEMM: C[M,N] = A[M,K] @ B[K,N], all row-major.
// 128x128 tile, TK=16, 256 threads, 8x8 per-thread fragment.
// M,N,K all divisible by tile sizes (4096 / {2048,512} / 2048).
// ---------------------------------------------------------------------------
__global__ __launch_bounds__(256) void gemm128(
    const float* __restrict__ A, const float* __restrict__ Bm,
    float* __restrict__ C, int M, int N, int K)
{
    __shared__ float As[16][128];   // transposed: As[k][m]
    __shared__ float Bs[16][128];   // Bs[k][n]

    const int tid = threadIdx.x;
    const int tx = tid & 15;        // n dim
    const int ty = tid >> 4;        // m dim
    const int m0 = blockIdx.y * 128;
    const int n0 = blockIdx.x * 128;

    float acc[8][8];
#pragma unroll
    for (int i = 0; i < 8; i++)
#pragma unroll
        for (int j = 0; j < 8; j++) acc[i][j] = 0.0f;

    for (int k0 = 0; k0 < K; k0 += 16) {
        // Load A tile 128x16 (512 float4)
#pragma unroll
        for (int i = 0; i < 2; i++) {
            int idx = tid + i * 256;            // 0..511
            int r = idx >> 2;                   // 0..127
            int c4 = idx & 3;                   // 0..3
            float4 va = *(const float4*)&A[(size_t)(m0 + r) * K + k0 + c4 * 4];
            As[c4 * 4 + 0][r] = va.x;
            As[c4 * 4 + 1][r] = va.y;
            As[c4 * 4 + 2][r] = va.z;
            As[c4 * 4 + 3][r] = va.w;
        }
        // Load B tile 16x128 (512 float4)
#pragma unroll
        for (int i = 0; i < 2; i++) {
            int idx = tid + i * 256;
            int r = idx >> 5;                   // 0..15
            int c4 = idx & 31;                  // 0..31
            *(float4*)&Bs[r][c4 * 4] =
                *(const float4*)&Bm[(size_t)(k0 + r) * N + n0 + c4 * 4];
        }
        __syncthreads();

#pragma unroll
        for (int kk = 0; kk < 16; kk++) {
            float4 a0 = *(const float4*)&As[kk][ty * 8];
            float4 a1 = *(const float4*)&As[kk][ty * 8 + 4];
            float4 b0 = *(const float4*)&Bs[kk][tx * 8];
            float4 b1 = *(const float4*)&Bs[kk][tx * 8 + 4];
            float a[8] = {a0.x, a0.y, a0.z, a0.w, a1.x, a1.y, a1.z, a1.w};
            float b[8] = {b0.x, b0.y, b0.z, b0.w, b1.x, b1.y, b1.z, b1.w};
#pragma unroll
            for (int i = 0; i < 8; i++)
#pragma unroll
                for (int j = 0; j < 8; j++)
                    acc[i][j] += a[i] * b[j];
        }
        __syncthreads();
    }

#pragma unroll
    for (int i = 0; i < 8; i++) {
        size_t row = (size_t)(m0 + ty * 8 + i) * N + n0 + tx * 8;
        float4 r0 = {acc[i][0], acc[i][1], acc[i][2], acc[i][3]};
        float4 r1 = {acc[i][4], acc[i][5], acc[i][6], acc[i][7]};
        *(float4*)&C[row]     = r0;
        *(float4*)&C[row + 4] = r1;
    }
}

// ---------------------------------------------------------------------------
// RoPE in-place on (B, T, heads, HD) tensor.
// ---------------------------------------------------------------------------
__global__ void rope_kernel(float* __restrict__ q,
                            const float* __restrict__ cosp,
                            const float* __restrict__ sinp,
                            int heads)
{
    int idx = blockIdx.x * blockDim.x + threadIdx.x;
    int total = BB * TT * heads * HALF;
    if (idx >= total) return;
    int i = idx % HALF;
    int h = (idx / HALF) % heads;
    int t = (idx / (HALF * heads)) % TT;
    int b = idx / (HALF * heads * TT);
    float c = cosp[t * HALF + i];
    float s = sinp[t * HALF + i];
    float* p = q + ((((size_t)b * TT + t) * heads + h) * HD);
    float x1 = p[i];
    float x2 = p[i + HALF];
    p[i]        = x1 * c - x2 * s;
    p[i + HALF] = x2 * c + x1 * s;
}

// ---------------------------------------------------------------------------
// Causal GQA flash attention, fp32.
// Q/K/V layouts: Q (b,t,h,d) stride NH*HD; K,V (b,t,kv,d) stride NKV*HD.
// Tile: BM=64 q rows x BN=64 kv cols, 256 threads (tx 0..15 cols/d, ty 0..15 rows).
// Score frag 4x4 per thread; O frag 4 rows x 8 d per thread.
// Smem: Qt[128][68] k-major (prescaled), Kt[128][68] k-major, Vs[64][128], Ps[64][68].
// ---------------------------------------------------------------------------
#define Bb 64
#define BNN 64
#define APAD 4
#define ATT_SMEM_FLOATS (128*(Bb+APAD) + 128*(BNN+APAD) + BNN*128 + Bb*(BNN+APAD))
#define ATT_SMEM_BYTES  (ATT_SMEM_FLOATS * 4)

__global__ __launch_bounds__(256) void attn_kernel(
    const float* __restrict__ Q, const float* __restrict__ Kc,
    const float* __restrict__ Vc, float* __restrict__ Oc)
{
    extern __shared__ float smf[];
    float* Qt = smf;                              // [128][BM+4]
    float* Kt = Qt + 128 * (Bb + APAD);           // [128][BN+4]
    float* Vs = Kt + 128 * (BNN + APAD);          // [BN][128]
    float* Ps = Vs + BNN * 128;                   // [BM][BN+4]

    const int tid = threadIdx.x;
    const int tx = tid & 15;
    const int ty = tid >> 4;
    // Reverse qt order: longest CTAs first (better tail with 1 CTA/SM occupancy)
    const int qt = (gridDim.x - 1) - blockIdx.x;
    const int h  = blockIdx.y;
    const int b  = blockIdx.z;
    const int kvh = h >> 2;                        // h / NREP
    const int qi0 = qt * Bb;
    const float scale = 0.08838834764831845f;      // 1/sqrt(128)

    // ---- load Q tile (transposed, pre-scaled) ----
    const float* qbase = Q + (((size_t)b * TT + qi0) * NH + h) * HD;
#pragma unroll
    for (int i = 0; i < 8; i++) {
        int idx = tid + i * 256;       // 0..2047
        int r  = idx >> 5;             // 0..63
        int d4 = idx & 31;             // 0..31
        float4 vq = *(const float4*)&qbase[(size_t)r * QN + d4 * 4];
        Qt[(d4 * 4 + 0) * (Bb + APAD) + r] = vq.x * scale;
        Qt[(d4 * 4 + 1) * (Bb + APAD) + r] = vq.y * scale;
        Qt[(d4 * 4 + 2) * (Bb + APAD) + r] = vq.z * scale;
        Qt[(d4 * 4 + 3) * (Bb + APAD) + r] = vq.w * scale;
    }

    float m_i[4], l_i[4], o[4][8];
#pragma unroll
    for (int ii = 0; ii < 4; ii++) {
        m_i[ii] = -1e30f;
        l_i[ii] = 0.0f;
#pragma unroll
        for (int dd = 0; dd < 8; dd++) o[ii][dd] = 0.0f;
    }

    const int ntiles = qi0 / BNN + 1;
    for (int kt = 0; kt < ntiles; kt++) {
        const int kj0 = kt * BNN;
        __syncthreads();   // protect Qt (first iter) / Kt,Vs from prior iter readers

        // ---- load K (transposed) and V tiles ----
        const float* kbase = Kc + (((size_t)b * TT + kj0) * NKV + kvh) * HD;
        const float* vbase = Vc + (((size_t)b * TT + kj0) * NKV + kvh) * HD;
#pragma unroll
        for (int i = 0; i < 8; i++) {
            int idx = tid + i * 256;
            int r  = idx >> 5;
            int d4 = idx & 31;
            float4 vk = *(const float4*)&kbase[(size_t)r * KN + d4 * 4];
            Kt[(d4 * 4 + 0) * (BNN + APAD) + r] = vk.x;
            Kt[(d4 * 4 + 1) * (BNN + APAD) + r] = vk.y;
            Kt[(d4 * 4 + 2) * (BNN + APAD) + r] = vk.z;
            Kt[(d4 * 4 + 3) * (BNN + APAD) + r] = vk.w;
            float4 vv = *(const float4*)&vbase[(size_t)r * KN + d4 * 4];
            *(float4*)&Vs[r * 128 + d4 * 4] = vv;
        }
        __syncthreads();

        // ---- S = Q K^T  (4x4 frag) ----
        float acc[4][4];
#pragma unroll
        for (int ii = 0; ii < 4; ii++)
#pragma unroll
            for (int jj = 0; jj < 4; jj++) acc[ii][jj] = 0.0f;

#pragma unroll 8
        for (int kk = 0; kk < HD; kk++) {
            float4 a = *(const float4*)&Qt[kk * (Bb + APAD) + ty * 4];
            float4 bb = *(const float4*)&Kt[kk * (BNN + APAD) + tx * 4];
            float av[4] = {a.x, a.y, a.z, a.w};
            float bv[4] = {bb.x, bb.y, bb.z, bb.w};
#pragma unroll
            for (int ii = 0; ii < 4; ii++)
#pragma unroll
                for (int jj = 0; jj < 4; jj++)
                    acc[ii][jj] += av[ii] * bv[jj];
        }

        // ---- causal mask (only diagonal tile needs it) ----
        if (kt == ntiles - 1) {
#pragma unroll
            for (int ii = 0; ii < 4; ii++) {
                int qi = qi0 + ty * 4 + ii;
#pragma unroll
                for (int jj = 0; jj < 4; jj++) {
                    int kj = kj0 + tx * 4 + jj;
                    if (kj > qi) acc[ii][jj] = -1e30f;
                }
            }
        }

        // ---- online softmax (reduce across 16 tx lanes via shfl) ----
#pragma unroll
        for (int ii = 0; ii < 4; ii++) {
            float tmax = fmaxf(fmaxf(acc[ii][0], acc[ii][1]),
                               fmaxf(acc[ii][2], acc[ii][3]));
#pragma unroll
            for (int off = 1; off < 16; off <<= 1)
                tmax = fmaxf(tmax, __shfl_xor_sync(0xffffffffu, tmax, off));
            float mnew = fmaxf(m_i[ii], tmax);
            float corr = __expf(m_i[ii] - mnew);
            float p0 = __expf(acc[ii][0] - mnew);
            float p1 = __expf(acc[ii][1] - mnew);
            float p2 = __expf(acc[ii][2] - mnew);
            float p3 = __expf(acc[ii][3] - mnew);
            float rsum = (p0 + p1) + (p2 + p3);
#pragma unroll
            for (int off = 1; off < 16; off <<= 1)
                rsum += __shfl_xor_sync(0xffffffffu, rsum, off);
            l_i[ii] = l_i[ii] * corr + rsum;
            m_i[ii] = mnew;
#pragma unroll
            for (int dd = 0; dd < 8; dd++) o[ii][dd] *= corr;
            float4 pv = {p0, p1, p2, p3};
            *(float4*)&Ps[(ty * 4 + ii) * (BNN + APAD) + tx * 4] = pv;
        }
        __syncwarp();   // Ps produced & consumed within the same warp

        // ---- O += P @ V  (4 rows x 8 d per thread) ----
#pragma unroll 4
        for (int j = 0; j < BNN; j++) {
            float4 v0 = *(const float4*)&Vs[j * 128 + tx * 8];
            float4 v1 = *(const float4*)&Vs[j * 128 + tx * 8 + 4];
#pragma unroll
            for (int ii = 0; ii < 4; ii++) {
                float p = Ps[(ty * 4 + ii) * (BNN + APAD) + j];
                o[ii][0] += p * v0.x;  o[ii][1] += p * v0.y;
                o[ii][2] += p * v0.z;  o[ii][3] += p * v0.w;
                o[ii][4] += p * v1.x;  o[ii][5] += p * v1.y;
                o[ii][6] += p * v1.z;  o[ii][7] += p * v1.w;
            }
        }
    }

    // ---- epilogue: normalize & store (b,t,h,d) ----
    float* obase = Oc + (((size_t)b * TT + qi0) * NH + h) * HD;
#pragma unroll
    for (int ii = 0; ii < 4; ii++) {
        float inv = 1.0f / l_i[ii];
        int r = ty * 4 + ii;
        float4 r0 = {o[ii][0] * inv, o[ii][1] * inv, o[ii][2] * inv, o[ii][3] * inv};
        float4 r1 = {o[ii][4] * inv, o[ii][5] * inv, o[ii][6] * inv, o[ii][7] * inv};
        *(float4*)&obase[(size_t)r * QN + tx * 8]     = r0;
        *(float4*)&obase[(size_t)r * QN + tx * 8 + 4] = r1;
    }
}

// ---------------------------------------------------------------------------
// Launch
// ---------------------------------------------------------------------------
extern "C" void kernel_launch(void* const* d_in, const int* in_sizes, int n_in,
                              void* d_out, int out_size)
{
    const float* x    = (const float*)d_in[0];
    const float* wq   = (const float*)d_in[1];
    const float* wk   = (const float*)d_in[2];
    const float* wv   = (const float*)d_in[3];
    const float* wo   = (const float*)d_in[4];
    const float* cosp = (const float*)d_in[5];
    const float* sinp = (const float*)d_in[6];
    float* out = (float*)d_out;

    float *qp, *kp, *vp, *ap;
    cudaGetSymbolAddress((void**)&qp, g_q);
    cudaGetSymbolAddress((void**)&kp, g_k);
    cudaGetSymbolAddress((void**)&vp, g_v);
    cudaGetSymbolAddress((void**)&ap, g_attn);

    cudaFuncSetAttribute(attn_kernel,
                         cudaFuncAttributeMaxDynamicSharedMemorySize,
                         ATT_SMEM_BYTES);

    // QKV projections
    gemm128<<<dim3(QN / 128, MTOT / 128), 256>>>(x, wq, qp, MTOT, QN, DM);
    gemm128<<<dim3(KN / 128, MTOT / 128), 256>>>(x, wk, kp, MTOT, KN, DM);
    gemm128<<<dim3(KN / 128, MTOT / 128), 256>>>(x, wv, vp, MTOT, KN, DM);

    // RoPE (in-place)
    {
        int tq = BB * TT * NH * HALF;
        rope_kernel<<<(tq + 255) / 256, 256>>>(qp, cosp, sinp, NH);
        int tk = BB * TT * NKV * HALF;
        rope_kernel<<<(tk + 255) / 256, 256>>>(kp, cosp, sinp, NKV);
    }

    // Flash attention
    attn_kernel<<<dim3(TT / Bb, NH, BB), 256, ATT_SMEM_BYTES>>>(qp, kp, vp, ap);

    // Output projection
    gemm128<<<dim3(QN / 128, MTOT / 128), 256>>>(ap, wo, out, MTOT, QN, DM);
}

// round 6
// speedup vs baseline: 1.5011x; 1.4985x over previous
#include <cuda_runtime.h>
#include <math.h>
#include <stdint.h>

// Problem constants
#define BB 2
#define TT 2048
#define DM 2048
#define NH 16
#define HD 128
#define NKV 4
#define NREP 4
#define HALF 64
#define MTOT (BB*TT)      // 4096
#define QN (NH*HD)        // 2048
#define KN (NKV*HD)       // 512

// Scratch (device globals: no allocations allowed)
__device__ float g_q[MTOT * QN];      // 32 MB
__device__ float g_k[MTOT * KN];      //  8 MB
__device__ float g_v[MTOT * KN];      //  8 MB
__device__ float g_attn[MTOT * QN];   // 32 MB
__device__ float g_wqT[DM * QN];      // 16 MB  (transposed weights, [N][K])
__device__ float g_wkT[DM * KN];      //  4 MB
__device__ float g_wvT[DM * KN];      //  4 MB
__device__ float g_woT[DM * DM];      // 16 MB

// ---------------------------------------------------------------------------
// Weight transpose: src [R][C] -> dst [C][R]
// ---------------------------------------------------------------------------
__global__ void transpose_kernel(const float* __restrict__ src,
                                 float* __restrict__ dst, int R, int C)
{
    __shared__ float t[32][33];
    int c0 = blockIdx.x * 32, r0 = blockIdx.y * 32;
    int x = threadIdx.x, y = threadIdx.y;   // block (32, 8)
#pragma unroll
    for (int i = 0; i < 32; i += 8)
        t[y + i][x] = src[(size_t)(r0 + y + i) * C + c0 + x];
    __syncthreads();
#pragma unroll
    for (int i = 0; i < 32; i += 8)
        dst[(size_t)(c0 + y + i) * R + r0 + x] = t[x][y + i];
}

// ---------------------------------------------------------------------------
// TF32 tensor-core GEMM: C[M,N] = A[M,K] @ B[K,N], with B supplied TRANSPOSED
// as Bt[N][K] row-major.  CTA tile 256x128, BK=16, 8 warps (4x2), warp tile
// 64x64 via mma.sync.m16n8k8.tf32.  Fragment-major smem layout: scatter on
// store (2-way conflicts via lane rotation), LDS.128/LDS.64 conflict-free
// fragment loads.
// ---------------------------------------------------------------------------
#define GBM 256
#define GBN 128
#define GBK 16

__device__ __forceinline__ uint32_t f2tf32(float x) {
    uint32_t u;
    asm("cvt.rna.tf32.f32 %0, %1;" : "=r"(u) : "f"(x));
    return u;
}

__device__ __forceinline__ void mma_tf32(float* d, const uint32_t* a,
                                         const uint32_t* b) {
    asm volatile(
        "mma.sync.aligned.m16n8k8.row.col.f32.tf32.tf32.f32 "
        "{%0,%1,%2,%3}, {%4,%5,%6,%7}, {%8,%9}, {%0,%1,%2,%3};\n"
        : "+f"(d[0]), "+f"(d[1]), "+f"(d[2]), "+f"(d[3])
        : "r"(a[0]), "r"(a[1]), "r"(a[2]), "r"(a[3]),
          "r"(b[0]), "r"(b[1]));
}

__device__ __forceinline__ void gemm_body(
    const float* __restrict__ A, const float* __restrict__ Bt,
    float* __restrict__ C, int M, int N, int K)
{
    __shared__ __align__(16) uint32_t As[GBM * GBK];   // 4096 words, frag-major
    __shared__ __align__(16) uint32_t Bs[GBN * GBK];   // 2048 words, frag-major

    const int tid  = threadIdx.x;
    const int lane = tid & 31;
    const int warp = tid >> 5;
    const int gid  = lane >> 2;
    const int tig  = lane & 3;
    const int wy   = warp >> 1;     // 0..3  (m band, 64 rows)
    const int wx   = warp & 1;      // 0..1  (n band, 64 cols)
    const int m0   = blockIdx.y * GBM;
    const int n0   = blockIdx.x * GBN;

    // loader decomposition
    const int c4    = tid & 3;      // which float4 along k (0..3)
    const int rbase = tid >> 2;     // 0..63
    const int ksS   = c4 >> 1;      // kstep of stored data
    const int khS   = c4 & 1;       // k-half within k8

    const float* Ag = A  + (size_t)(m0 + rbase) * K + c4 * 4;
    const float* Bg = Bt + (size_t)(n0 + rbase) * K + c4 * 4;

    float acc[4][8][4];
#pragma unroll
    for (int mt = 0; mt < 4; mt++)
#pragma unroll
        for (int nt = 0; nt < 8; nt++)
#pragma unroll
            for (int r = 0; r < 4; r++) acc[mt][nt][r] = 0.0f;

    float4 pa[4], pb[2];
    const int NC = K / GBK;

    // ---- prologue: load + store chunk 0 ----
#pragma unroll
    for (int i = 0; i < 4; i++)
        pa[i] = *(const float4*)&Ag[(size_t)(64 * i) * K];
#pragma unroll
    for (int i = 0; i < 2; i++)
        pb[i] = *(const float4*)&Bg[(size_t)(64 * i) * K];

    {
        // scatter-store A
#pragma unroll
        for (int i = 0; i < 4; i++) {
            int r  = rbase + 64 * i;
            int Mi = r >> 4, g = r & 7, rh = (r >> 3) & 1;
            int base = ((Mi * 2 + ksS) * 32 + g * 4);
            int roff = rh + 2 * khS;
            float e[4] = {pa[i].x, pa[i].y, pa[i].z, pa[i].w};
#pragma unroll
            for (int jj = 0; jj < 4; jj++) {
                int j = (jj + c4 + g) & 3;
                As[(base + j) * 4 + roff] = f2tf32(e[j]);
            }
        }
        // scatter-store B
#pragma unroll
        for (int i = 0; i < 2; i++) {
            int r  = rbase + 64 * i;
            int Ni = r >> 3, g = r & 7;
            int base = ((Ni * 2 + ksS) * 32 + g * 4);
            float e[4] = {pb[i].x, pb[i].y, pb[i].z, pb[i].w};
#pragma unroll
            for (int jj = 0; jj < 4; jj++) {
                int j = (jj + c4 + g) & 3;
                Bs[(base + j) * 2 + khS] = f2tf32(e[j]);
            }
        }
    }
    __syncthreads();

    for (int kc = 0; kc < NC; kc++) {
        // prefetch next chunk into registers
        if (kc + 1 < NC) {
            size_t koff = (size_t)(kc + 1) * GBK;
#pragma unroll
            for (int i = 0; i < 4; i++)
                pa[i] = *(const float4*)&Ag[(size_t)(64 * i) * K + koff];
#pragma unroll
            for (int i = 0; i < 2; i++)
                pb[i] = *(const float4*)&Bg[(size_t)(64 * i) * K + koff];
        }

        // ---- compute on smem (2 ksteps x 32 mma) ----
#pragma unroll
        for (int ks = 0; ks < 2; ks++) {
            uint32_t a[4][4], b[8][2];
#pragma unroll
            for (int mt = 0; mt < 4; mt++) {
                int Mi = wy * 4 + mt;
                uint4 v = *(const uint4*)&As[((Mi * 2 + ks) * 32 + lane) * 4];
                a[mt][0] = v.x; a[mt][1] = v.y; a[mt][2] = v.z; a[mt][3] = v.w;
            }
#pragma unroll
            for (int nt = 0; nt < 8; nt++) {
                int Ni = wx * 8 + nt;
                uint2 v = *(const uint2*)&Bs[((Ni * 2 + ks) * 32 + lane) * 2];
                b[nt][0] = v.x; b[nt][1] = v.y;
            }
#pragma unroll
            for (int mt = 0; mt < 4; mt++)
#pragma unroll
                for (int nt = 0; nt < 8; nt++)
                    mma_tf32(acc[mt][nt], a[mt], b[nt]);
        }

        if (kc + 1 < NC) {
            __syncthreads();
            // scatter-store next chunk
#pragma unroll
            for (int i = 0; i < 4; i++) {
                int r  = rbase + 64 * i;
                int Mi = r >> 4, g = r & 7, rh = (r >> 3) & 1;
                int base = ((Mi * 2 + ksS) * 32 + g * 4);
                int roff = rh + 2 * khS;
                float e[4] = {pa[i].x, pa[i].y, pa[i].z, pa[i].w};
#pragma unroll
                for (int jj = 0; jj < 4; jj++) {
                    int j = (jj + c4 + g) & 3;
                    As[(base + j) * 4 + roff] = f2tf32(e[j]);
                }
            }
#pragma unroll
            for (int i = 0; i < 2; i++) {
                int r  = rbase + 64 * i;
                int Ni = r >> 3, g = r & 7;
                int base = ((Ni * 2 + ksS) * 32 + g * 4);
                float e[4] = {pb[i].x, pb[i].y, pb[i].z, pb[i].w};
#pragma unroll
                for (int jj = 0; jj < 4; jj++) {
                    int j = (jj + c4 + g) & 3;
                    Bs[(base + j) * 2 + khS] = f2tf32(e[j]);
                }
            }
            __syncthreads();
        }
    }

    // ---- epilogue ----
#pragma unroll
    for (int mt = 0; mt < 4; mt++) {
        int row = m0 + wy * 64 + mt * 16 + gid;
#pragma unroll
        for (int nt = 0; nt < 8; nt++) {
            int col = n0 + wx * 64 + nt * 8 + tig * 2;
            float2 lo = {acc[mt][nt][0], acc[mt][nt][1]};
            float2 hi = {acc[mt][nt][2], acc[mt][nt][3]};
            *(float2*)&C[(size_t)row * N + col]       = lo;
            *(float2*)&C[(size_t)(row + 8) * N + col] = hi;
        }
    }
}

__global__ __launch_bounds__(256, 1) void gemm_tf32(
    const float* __restrict__ A, const float* __restrict__ Bt,
    float* __restrict__ C, int M, int N, int K)
{
    gemm_body(A, Bt, C, M, N, K);
}

// K and V projections fused via blockIdx.z
__global__ __launch_bounds__(256, 1) void gemm_tf32_kv(
    const float* __restrict__ A,
    const float* __restrict__ BtK, const float* __restrict__ BtV,
    float* __restrict__ Ck, float* __restrict__ Cv, int M, int N, int K)
{
    const float* Bt = blockIdx.z ? BtV : BtK;
    float* C = blockIdx.z ? Cv : Ck;
    gemm_body(A, Bt, C, M, N, K);
}

// ---------------------------------------------------------------------------
// RoPE in-place on (B, T, heads, HD) tensor.
// ---------------------------------------------------------------------------
__global__ void rope_kernel(float* __restrict__ q,
                            const float* __restrict__ cosp,
                            const float* __restrict__ sinp,
                            int heads)
{
    int idx = blockIdx.x * blockDim.x + threadIdx.x;
    int total = BB * TT * heads * HALF;
    if (idx >= total) return;
    int i = idx % HALF;
    int h = (idx / HALF) % heads;
    int t = (idx / (HALF * heads)) % TT;
    int b = idx / (HALF * heads * TT);
    float c = cosp[t * HALF + i];
    float s = sinp[t * HALF + i];
    float* p = q + ((((size_t)b * TT + t) * heads + h) * HD);
    float x1 = p[i];
    float x2 = p[i + HALF];
    p[i]        = x1 * c - x2 * s;
    p[i + HALF] = x2 * c + x1 * s;
}

// ---------------------------------------------------------------------------
// Causal GQA flash attention, fp32 (unchanged from R5 passing version).
// ---------------------------------------------------------------------------
#define Bb 64
#define BNN 64
#define APAD 4
#define ATT_SMEM_FLOATS (128*(Bb+APAD) + 128*(BNN+APAD) + BNN*128 + Bb*(BNN+APAD))
#define ATT_SMEM_BYTES  (ATT_SMEM_FLOATS * 4)

__global__ __launch_bounds__(256) void attn_kernel(
    const float* __restrict__ Q, const float* __restrict__ Kc,
    const float* __restrict__ Vc, float* __restrict__ Oc)
{
    extern __shared__ float smf[];
    float* Qt = smf;
    float* Kt = Qt + 128 * (Bb + APAD);
    float* Vs = Kt + 128 * (BNN + APAD);
    float* Ps = Vs + BNN * 128;

    const int tid = threadIdx.x;
    const int tx = tid & 15;
    const int ty = tid >> 4;
    const int qt = (gridDim.x - 1) - blockIdx.x;
    const int h  = blockIdx.y;
    const int b  = blockIdx.z;
    const int kvh = h >> 2;
    const int qi0 = qt * Bb;
    const float scale = 0.08838834764831845f;

    const float* qbase = Q + (((size_t)b * TT + qi0) * NH + h) * HD;
#pragma unroll
    for (int i = 0; i < 8; i++) {
        int idx = tid + i * 256;
        int r  = idx >> 5;
        int d4 = idx & 31;
        float4 vq = *(const float4*)&qbase[(size_t)r * QN + d4 * 4];
        Qt[(d4 * 4 + 0) * (Bb + APAD) + r] = vq.x * scale;
        Qt[(d4 * 4 + 1) * (Bb + APAD) + r] = vq.y * scale;
        Qt[(d4 * 4 + 2) * (Bb + APAD) + r] = vq.z * scale;
        Qt[(d4 * 4 + 3) * (Bb + APAD) + r] = vq.w * scale;
    }

    float m_i[4], l_i[4], o[4][8];
#pragma unroll
    for (int ii = 0; ii < 4; ii++) {
        m_i[ii] = -1e30f;
        l_i[ii] = 0.0f;
#pragma unroll
        for (int dd = 0; dd < 8; dd++) o[ii][dd] = 0.0f;
    }

    const int ntiles = qi0 / BNN + 1;
    for (int kt = 0; kt < ntiles; kt++) {
        const int kj0 = kt * BNN;
        __syncthreads();

        const float* kbase = Kc + (((size_t)b * TT + kj0) * NKV + kvh) * HD;
        const float* vbase = Vc + (((size_t)b * TT + kj0) * NKV + kvh) * HD;
#pragma unroll
        for (int i = 0; i < 8; i++) {
            int idx = tid + i * 256;
            int r  = idx >> 5;
            int d4 = idx & 31;
            float4 vk = *(const float4*)&kbase[(size_t)r * KN + d4 * 4];
            Kt[(d4 * 4 + 0) * (BNN + APAD) + r] = vk.x;
            Kt[(d4 * 4 + 1) * (BNN + APAD) + r] = vk.y;
            Kt[(d4 * 4 + 2) * (BNN + APAD) + r] = vk.z;
            Kt[(d4 * 4 + 3) * (BNN + APAD) + r] = vk.w;
            float4 vv = *(const float4*)&vbase[(size_t)r * KN + d4 * 4];
            *(float4*)&Vs[r * 128 + d4 * 4] = vv;
        }
        __syncthreads();

        float acc[4][4];
#pragma unroll
        for (int ii = 0; ii < 4; ii++)
#pragma unroll
            for (int jj = 0; jj < 4; jj++) acc[ii][jj] = 0.0f;

#pragma unroll 8
        for (int kk = 0; kk < HD; kk++) {
            float4 a = *(const float4*)&Qt[kk * (Bb + APAD) + ty * 4];
            float4 bb = *(const float4*)&Kt[kk * (BNN + APAD) + tx * 4];
            float av[4] = {a.x, a.y, a.z, a.w};
            float bv[4] = {bb.x, bb.y, bb.z, bb.w};
#pragma unroll
            for (int ii = 0; ii < 4; ii++)
#pragma unroll
                for (int jj = 0; jj < 4; jj++)
                    acc[ii][jj] += av[ii] * bv[jj];
        }

        if (kt == ntiles - 1) {
#pragma unroll
            for (int ii = 0; ii < 4; ii++) {
                int qi = qi0 + ty * 4 + ii;
#pragma unroll
                for (int jj = 0; jj < 4; jj++) {
                    int kj = kj0 + tx * 4 + jj;
                    if (kj > qi) acc[ii][jj] = -1e30f;
                }
            }
        }

#pragma unroll
        for (int ii = 0; ii < 4; ii++) {
            float tmax = fmaxf(fmaxf(acc[ii][0], acc[ii][1]),
                               fmaxf(acc[ii][2], acc[ii][3]));
#pragma unroll
            for (int off = 1; off < 16; off <<= 1)
                tmax = fmaxf(tmax, __shfl_xor_sync(0xffffffffu, tmax, off));
            float mnew = fmaxf(m_i[ii], tmax);
            float corr = __expf(m_i[ii] - mnew);
            float p0 = __expf(acc[ii][0] - mnew);
            float p1 = __expf(acc[ii][1] - mnew);
            float p2 = __expf(acc[ii][2] - mnew);
            float p3 = __expf(acc[ii][3] - mnew);
            float rsum = (p0 + p1) + (p2 + p3);
#pragma unroll
            for (int off = 1; off < 16; off <<= 1)
                rsum += __shfl_xor_sync(0xffffffffu, rsum, off);
            l_i[ii] = l_i[ii] * corr + rsum;
            m_i[ii] = mnew;
#pragma unroll
            for (int dd = 0; dd < 8; dd++) o[ii][dd] *= corr;
            float4 pv = {p0, p1, p2, p3};
            *(float4*)&Ps[(ty * 4 + ii) * (BNN + APAD) + tx * 4] = pv;
        }
        __syncwarp();

#pragma unroll 4
        for (int j = 0; j < BNN; j++) {
            float4 v0 = *(const float4*)&Vs[j * 128 + tx * 8];
            float4 v1 = *(const float4*)&Vs[j * 128 + tx * 8 + 4];
#pragma unroll
            for (int ii = 0; ii < 4; ii++) {
                float p = Ps[(ty * 4 + ii) * (BNN + APAD) + j];
                o[ii][0] += p * v0.x;  o[ii][1] += p * v0.y;
                o[ii][2] += p * v0.z;  o[ii][3] += p * v0.w;
                o[ii][4] += p * v1.x;  o[ii][5] += p * v1.y;
                o[ii][6] += p * v1.z;  o[ii][7] += p * v1.w;
            }
        }
    }

    float* obase = Oc + (((size_t)b * TT + qi0) * NH + h) * HD;
#pragma unroll
    for (int ii = 0; ii < 4; ii++) {
        float inv = 1.0f / l_i[ii];
        int r = ty * 4 + ii;
        float4 r0 = {o[ii][0] * inv, o[ii][1] * inv, o[ii][2] * inv, o[ii][3] * inv};
        float4 r1 = {o[ii][4] * inv, o[ii][5] * inv, o[ii][6] * inv, o[ii][7] * inv};
        *(float4*)&obase[(size_t)r * QN + tx * 8]     = r0;
        *(float4*)&obase[(size_t)r * QN + tx * 8 + 4] = r1;
    }
}

// ---------------------------------------------------------------------------
// Launch
// ---------------------------------------------------------------------------
extern "C" void kernel_launch(void* const* d_in, const int* in_sizes, int n_in,
                              void* d_out, int out_size)
{
    const float* x    = (const float*)d_in[0];
    const float* wq   = (const float*)d_in[1];
    const float* wk   = (const float*)d_in[2];
    const float* wv   = (const float*)d_in[3];
    const float* wo   = (const float*)d_in[4];
    const float* cosp = (const float*)d_in[5];
    const float* sinp = (const float*)d_in[6];
    float* out = (float*)d_out;

    float *qp, *kp, *vp, *ap, *wqT, *wkT, *wvT, *woT;
    cudaGetSymbolAddress((void**)&qp,  g_q);
    cudaGetSymbolAddress((void**)&kp,  g_k);
    cudaGetSymbolAddress((void**)&vp,  g_v);
    cudaGetSymbolAddress((void**)&ap,  g_attn);
    cudaGetSymbolAddress((void**)&wqT, g_wqT);
    cudaGetSymbolAddress((void**)&wkT, g_wkT);
    cudaGetSymbolAddress((void**)&wvT, g_wvT);
    cudaGetSymbolAddress((void**)&woT, g_woT);

    cudaFuncSetAttribute(attn_kernel,
                         cudaFuncAttributeMaxDynamicSharedMemorySize,
                         ATT_SMEM_BYTES);

    // Transpose weights to [N][K]
    dim3 tb(32, 8);
    transpose_kernel<<<dim3(QN / 32, DM / 32), tb>>>(wq, wqT, DM, QN);
    transpose_kernel<<<dim3(KN / 32, DM / 32), tb>>>(wk, wkT, DM, KN);
    transpose_kernel<<<dim3(KN / 32, DM / 32), tb>>>(wv, wvT, DM, KN);
    transpose_kernel<<<dim3(QN / 32, DM / 32), tb>>>(wo, woT, DM, DM);

    // QKV projections (tf32 tensor cores)
    gemm_tf32<<<dim3(QN / GBN, MTOT / GBM), 256>>>(x, wqT, qp, MTOT, QN, DM);
    gemm_tf32_kv<<<dim3(KN / GBN, MTOT / GBM, 2), 256>>>(
        x, wkT, wvT, kp, vp, MTOT, KN, DM);

    // RoPE (in-place)
    {
        int tq = BB * TT * NH * HALF;
        rope_kernel<<<(tq + 255) / 256, 256>>>(qp, cosp, sinp, NH);
        int tk = BB * TT * NKV * HALF;
        rope_kernel<<<(tk + 255) / 256, 256>>>(kp, cosp, sinp, NKV);
    }

    // Flash attention (fp32)
    attn_kernel<<<dim3(TT / Bb, NH, BB), 256, ATT_SMEM_BYTES>>>(qp, kp, vp, ap);

    // Output projection (tf32 tensor cores)
    gemm_tf32<<<dim3(QN / GBN, MTOT / GBM), 256>>>(ap, woT, out, MTOT, QN, DM);
}

// round 7
// speedup vs baseline: 3.0536x; 2.0343x over previous
#include <cuda_runtime.h>
#include <cuda_fp16.h>
#include <math.h>
#include <stdint.h>

// Problem constants
#define BB 2
#define TT 2048
#define DM 2048
#define NH 16
#define HD 128
#define NKV 4
#define NREP 4
#define HALF 64
#define MTOT (BB*TT)      // 4096
#define QN (NH*HD)        // 2048
#define KN (NKV*HD)       // 512

// Scratch (device globals: no allocations allowed)
__device__ float g_q[MTOT * QN];      // 32 MB
__device__ float g_k[MTOT * KN];      //  8 MB
__device__ float g_v[MTOT * KN];      //  8 MB
__device__ float g_attn[MTOT * QN];   // 32 MB
__device__ float g_wqT[DM * QN];      // 16 MB  (transposed weights, [N][K])
__device__ float g_wkT[DM * KN];      //  4 MB
__device__ float g_wvT[DM * KN];      //  4 MB
__device__ float g_woT[DM * DM];      // 16 MB

// ---------------------------------------------------------------------------
// Weight transpose: src [R][C] -> dst [C][R]
// ---------------------------------------------------------------------------
__global__ void transpose_kernel(const float* __restrict__ src,
                                 float* __restrict__ dst, int R, int C)
{
    __shared__ float t[32][33];
    int c0 = blockIdx.x * 32, r0 = blockIdx.y * 32;
    int x = threadIdx.x, y = threadIdx.y;   // block (32, 8)
#pragma unroll
    for (int i = 0; i < 32; i += 8)
        t[y + i][x] = src[(size_t)(r0 + y + i) * C + c0 + x];
    __syncthreads();
#pragma unroll
    for (int i = 0; i < 32; i += 8)
        dst[(size_t)(c0 + y + i) * R + r0 + x] = t[x][y + i];
}

// ---------------------------------------------------------------------------
// MMA helpers
// ---------------------------------------------------------------------------
__device__ __forceinline__ uint32_t f2tf32(float x) {
    uint32_t u;
    asm("cvt.rna.tf32.f32 %0, %1;" : "=r"(u) : "f"(x));
    return u;
}

__device__ __forceinline__ void mma_tf32(float* d, const uint32_t* a,
                                         const uint32_t* b) {
    asm volatile(
        "mma.sync.aligned.m16n8k8.row.col.f32.tf32.tf32.f32 "
        "{%0,%1,%2,%3}, {%4,%5,%6,%7}, {%8,%9}, {%0,%1,%2,%3};\n"
        : "+f"(d[0]), "+f"(d[1]), "+f"(d[2]), "+f"(d[3])
        : "r"(a[0]), "r"(a[1]), "r"(a[2]), "r"(a[3]),
          "r"(b[0]), "r"(b[1]));
}

__device__ __forceinline__ void mma_fp16(float* d, const uint32_t* a,
                                         uint32_t b0, uint32_t b1) {
    asm volatile(
        "mma.sync.aligned.m16n8k16.row.col.f32.f16.f16.f32 "
        "{%0,%1,%2,%3}, {%4,%5,%6,%7}, {%8,%9}, {%0,%1,%2,%3};\n"
        : "+f"(d[0]), "+f"(d[1]), "+f"(d[2]), "+f"(d[3])
        : "r"(a[0]), "r"(a[1]), "r"(a[2]), "r"(a[3]),
          "r"(b0), "r"(b1));
}

// ---------------------------------------------------------------------------
// TF32 tensor-core GEMM (unchanged from R6 passing version).
// ---------------------------------------------------------------------------
#define GBM 256
#define GBN 128
#define GBK 16

__device__ __forceinline__ void gemm_body(
    const float* __restrict__ A, const float* __restrict__ Bt,
    float* __restrict__ C, int M, int N, int K)
{
    __shared__ __align__(16) uint32_t As[GBM * GBK];
    __shared__ __align__(16) uint32_t Bs[GBN * GBK];

    const int tid  = threadIdx.x;
    const int lane = tid & 31;
    const int warp = tid >> 5;
    const int gid  = lane >> 2;
    const int tig  = lane & 3;
    const int wy   = warp >> 1;
    const int wx   = warp & 1;
    const int m0   = blockIdx.y * GBM;
    const int n0   = blockIdx.x * GBN;

    const int c4    = tid & 3;
    const int rbase = tid >> 2;
    const int ksS   = c4 >> 1;
    const int khS   = c4 & 1;

    const float* Ag = A  + (size_t)(m0 + rbase) * K + c4 * 4;
    const float* Bg = Bt + (size_t)(n0 + rbase) * K + c4 * 4;

    float acc[4][8][4];
#pragma unroll
    for (int mt = 0; mt < 4; mt++)
#pragma unroll
        for (int nt = 0; nt < 8; nt++)
#pragma unroll
            for (int r = 0; r < 4; r++) acc[mt][nt][r] = 0.0f;

    float4 pa[4], pb[2];
    const int NC = K / GBK;

#pragma unroll
    for (int i = 0; i < 4; i++)
        pa[i] = *(const float4*)&Ag[(size_t)(64 * i) * K];
#pragma unroll
    for (int i = 0; i < 2; i++)
        pb[i] = *(const float4*)&Bg[(size_t)(64 * i) * K];

    {
#pragma unroll
        for (int i = 0; i < 4; i++) {
            int r  = rbase + 64 * i;
            int Mi = r >> 4, g = r & 7, rh = (r >> 3) & 1;
            int base = ((Mi * 2 + ksS) * 32 + g * 4);
            int roff = rh + 2 * khS;
            float e[4] = {pa[i].x, pa[i].y, pa[i].z, pa[i].w};
#pragma unroll
            for (int jj = 0; jj < 4; jj++) {
                int j = (jj + c4 + g) & 3;
                As[(base + j) * 4 + roff] = f2tf32(e[j]);
            }
        }
#pragma unroll
        for (int i = 0; i < 2; i++) {
            int r  = rbase + 64 * i;
            int Ni = r >> 3, g = r & 7;
            int base = ((Ni * 2 + ksS) * 32 + g * 4);
            float e[4] = {pb[i].x, pb[i].y, pb[i].z, pb[i].w};
#pragma unroll
            for (int jj = 0; jj < 4; jj++) {
                int j = (jj + c4 + g) & 3;
                Bs[(base + j) * 2 + khS] = f2tf32(e[j]);
            }
        }
    }
    __syncthreads();

    for (int kc = 0; kc < NC; kc++) {
        if (kc + 1 < NC) {
            size_t koff = (size_t)(kc + 1) * GBK;
#pragma unroll
            for (int i = 0; i < 4; i++)
                pa[i] = *(const float4*)&Ag[(size_t)(64 * i) * K + koff];
#pragma unroll
            for (int i = 0; i < 2; i++)
                pb[i] = *(const float4*)&Bg[(size_t)(64 * i) * K + koff];
        }

#pragma unroll
        for (int ks = 0; ks < 2; ks++) {
            uint32_t a[4][4], b[8][2];
#pragma unroll
            for (int mt = 0; mt < 4; mt++) {
                int Mi = wy * 4 + mt;
                uint4 v = *(const uint4*)&As[((Mi * 2 + ks) * 32 + lane) * 4];
                a[mt][0] = v.x; a[mt][1] = v.y; a[mt][2] = v.z; a[mt][3] = v.w;
            }
#pragma unroll
            for (int nt = 0; nt < 8; nt++) {
                int Ni = wx * 8 + nt;
                uint2 v = *(const uint2*)&Bs[((Ni * 2 + ks) * 32 + lane) * 2];
                b[nt][0] = v.x; b[nt][1] = v.y;
            }
#pragma unroll
            for (int mt = 0; mt < 4; mt++)
#pragma unroll
                for (int nt = 0; nt < 8; nt++)
                    mma_tf32(acc[mt][nt], a[mt], b[nt]);
        }

        if (kc + 1 < NC) {
            __syncthreads();
#pragma unroll
            for (int i = 0; i < 4; i++) {
                int r  = rbase + 64 * i;
                int Mi = r >> 4, g = r & 7, rh = (r >> 3) & 1;
                int base = ((Mi * 2 + ksS) * 32 + g * 4);
                int roff = rh + 2 * khS;
                float e[4] = {pa[i].x, pa[i].y, pa[i].z, pa[i].w};
#pragma unroll
                for (int jj = 0; jj < 4; jj++) {
                    int j = (jj + c4 + g) & 3;
                    As[(base + j) * 4 + roff] = f2tf32(e[j]);
                }
            }
#pragma unroll
            for (int i = 0; i < 2; i++) {
                int r  = rbase + 64 * i;
                int Ni = r >> 3, g = r & 7;
                int base = ((Ni * 2 + ksS) * 32 + g * 4);
                float e[4] = {pb[i].x, pb[i].y, pb[i].z, pb[i].w};
#pragma unroll
                for (int jj = 0; jj < 4; jj++) {
                    int j = (jj + c4 + g) & 3;
                    Bs[(base + j) * 2 + khS] = f2tf32(e[j]);
                }
            }
            __syncthreads();
        }
    }

#pragma unroll
    for (int mt = 0; mt < 4; mt++) {
        int row = m0 + wy * 64 + mt * 16 + gid;
#pragma unroll
        for (int nt = 0; nt < 8; nt++) {
            int col = n0 + wx * 64 + nt * 8 + tig * 2;
            float2 lo = {acc[mt][nt][0], acc[mt][nt][1]};
            float2 hi = {acc[mt][nt][2], acc[mt][nt][3]};
            *(float2*)&C[(size_t)row * N + col]       = lo;
            *(float2*)&C[(size_t)(row + 8) * N + col] = hi;
        }
    }
}

__global__ __launch_bounds__(256, 1) void gemm_tf32(
    const float* __restrict__ A, const float* __restrict__ Bt,
    float* __restrict__ C, int M, int N, int K)
{
    gemm_body(A, Bt, C, M, N, K);
}

__global__ __launch_bounds__(256, 1) void gemm_tf32_kv(
    const float* __restrict__ A,
    const float* __restrict__ BtK, const float* __restrict__ BtV,
    float* __restrict__ Ck, float* __restrict__ Cv, int M, int N, int K)
{
    const float* Bt = blockIdx.z ? BtV : BtK;
    float* C = blockIdx.z ? Cv : Ck;
    gemm_body(A, Bt, C, M, N, K);
}

// ---------------------------------------------------------------------------
// RoPE in-place on (B, T, heads, HD) tensor.
// ---------------------------------------------------------------------------
__global__ void rope_kernel(float* __restrict__ q,
                            const float* __restrict__ cosp,
                            const float* __restrict__ sinp,
                            int heads)
{
    int idx = blockIdx.x * blockDim.x + threadIdx.x;
    int total = BB * TT * heads * HALF;
    if (idx >= total) return;
    int i = idx % HALF;
    int h = (idx / HALF) % heads;
    int t = (idx / (HALF * heads)) % TT;
    int b = idx / (HALF * heads * TT);
    float c = cosp[t * HALF + i];
    float s = sinp[t * HALF + i];
    float* p = q + ((((size_t)b * TT + t) * heads + h) * HD);
    float x1 = p[i];
    float x2 = p[i + HALF];
    p[i]        = x1 * c - x2 * s;
    p[i + HALF] = x2 * c + x1 * s;
}

// ---------------------------------------------------------------------------
// Tensor-core causal GQA flash attention.
//   S = QK^T via m16n8k8 tf32, softmax in registers (warp-local rows),
//   P kept in registers as fp16 A-fragments, O += P@V via m16n8k16 f16.
// CTA: 128 q rows x full head-dim; key tiles of 64. 256 threads (8 warps),
// warp w owns rows [w*16, w*16+16).
// Smem: Qs[128][132] tf32 words, Ks[64][132] tf32 words, Vw[128][36] half2.
// ---------------------------------------------------------------------------
#define AQS 132
#define AVS 36
#define ATTN_SMEM_BYTES ((128*AQS + 64*AQS + 128*AVS) * 4)   // 119808

__global__ __launch_bounds__(256, 1) void attn_mma_kernel(
    const float* __restrict__ Q, const float* __restrict__ Kc,
    const float* __restrict__ Vc, float* __restrict__ Oc)
{
    extern __shared__ uint32_t smw[];
    uint32_t* Qs = smw;                  // [128][132] tf32 bits
    uint32_t* Ks = Qs + 128 * AQS;       // [64][132] tf32 bits
    uint32_t* Vw = Ks + 64 * AQS;        // [128][36] half2 (V^T, key-pairs)

    const int tid  = threadIdx.x;
    const int lane = tid & 31;
    const int warp = tid >> 5;
    const int gid  = lane >> 2;
    const int tig  = lane & 3;
    const int qt   = (gridDim.x - 1) - blockIdx.x;   // long CTAs first
    const int h    = blockIdx.y;
    const int b    = blockIdx.z;
    const int kvh  = h >> 2;
    const int qi0  = qt * 128;
    const float scale = 0.08838834764831845f;  // 1/sqrt(128)

    // ---- stage Q (scaled, tf32) ----
    const float* qbase = Q + (((size_t)b * TT + qi0) * NH + h) * HD;
#pragma unroll
    for (int i = 0; i < 16; i++) {
        int idx = tid + i * 256;
        int r = idx >> 5, d4 = idx & 31;
        float4 v = *(const float4*)&qbase[(size_t)r * QN + d4 * 4];
        uint4 u = { f2tf32(v.x * scale), f2tf32(v.y * scale),
                    f2tf32(v.z * scale), f2tf32(v.w * scale) };
        *(uint4*)&Qs[r * AQS + d4 * 4] = u;
    }

    float m_i[2] = {-1e30f, -1e30f};
    float l_i[2] = {0.0f, 0.0f};
    float o[16][4];
#pragma unroll
    for (int nt = 0; nt < 16; nt++)
#pragma unroll
        for (int r = 0; r < 4; r++) o[nt][r] = 0.0f;

    const int arow = warp * 16 + gid;
    const int ntiles = qi0 / 64 + 2;

    for (int kt = 0; kt < ntiles; kt++) {
        const int kj0 = kt * 64;
        __syncthreads();

        // ---- stage K (tf32, row-major [key][d]) ----
        const float* kbase = Kc + (((size_t)b * TT + kj0) * NKV + kvh) * HD;
#pragma unroll
        for (int i = 0; i < 8; i++) {
            int idx = tid + i * 256;
            int r = idx >> 5, d4 = idx & 31;
            float4 v = *(const float4*)&kbase[(size_t)r * KN + d4 * 4];
            uint4 u = { f2tf32(v.x), f2tf32(v.y), f2tf32(v.z), f2tf32(v.w) };
            *(uint4*)&Ks[r * AQS + d4 * 4] = u;
        }
        // ---- stage V (fp16, transposed: Vw[d][keypair]) ----
        const float* vbase = Vc + (((size_t)b * TT + kj0) * NKV + kvh) * HD;
#pragma unroll
        for (int i = 0; i < 16; i++) {
            int idx = i * 256 + tid;
            int dlo = idx & 7, kp = (idx >> 3) & 31, dhi = idx >> 8;
            int d = dhi * 8 + dlo;
            float f0 = vbase[(size_t)(2 * kp)     * KN + d];
            float f1 = vbase[(size_t)(2 * kp + 1) * KN + d];
            __half2 hv = __floats2half2_rn(f0, f1);
            Vw[d * AVS + kp] = *(uint32_t*)&hv;
        }
        __syncthreads();

        // ---- S = Q K^T (tf32 mma, warp tile 16x64) ----
        float s[8][4];
#pragma unroll
        for (int nt = 0; nt < 8; nt++)
#pragma unroll
            for (int r = 0; r < 4; r++) s[nt][r] = 0.0f;

#pragma unroll
        for (int ks = 0; ks < 16; ks++) {
            uint32_t a[4];
            int ab = arow * AQS + ks * 8 + tig;
            a[0] = Qs[ab];
            a[1] = Qs[ab + 8 * AQS];
            a[2] = Qs[ab + 4];
            a[3] = Qs[ab + 8 * AQS + 4];
#pragma unroll
            for (int nt = 0; nt < 8; nt++) {
                int kb = (nt * 8 + gid) * AQS + ks * 8 + tig;
                uint32_t bb[2] = { Ks[kb], Ks[kb + 4] };
                mma_tf32(s[nt], a, bb);
            }
        }

        // ---- causal mask (only last two key tiles touch the diagonal) ----
        if (kt >= ntiles - 2) {
#pragma unroll
            for (int nt = 0; nt < 8; nt++)
#pragma unroll
                for (int r = 0; r < 4; r++) {
                    int row = qi0 + warp * 16 + gid + (r >> 1) * 8;
                    int col = kj0 + nt * 8 + 2 * tig + (r & 1);
                    if (col > row) s[nt][r] = -1e30f;
                }
        }

        // ---- online softmax (rows live in one warp; reduce over tig quad) ----
        uint32_t ph[8][2];
#pragma unroll
        for (int e = 0; e < 2; e++) {
            float mx = -1e30f;
#pragma unroll
            for (int nt = 0; nt < 8; nt++)
                mx = fmaxf(mx, fmaxf(s[nt][2 * e], s[nt][2 * e + 1]));
            mx = fmaxf(mx, __shfl_xor_sync(0xffffffffu, mx, 1));
            mx = fmaxf(mx, __shfl_xor_sync(0xffffffffu, mx, 2));
            float mnew = fmaxf(m_i[e], mx);
            float corr = __expf(m_i[e] - mnew);
            m_i[e] = mnew;
            float rsum = 0.0f;
#pragma unroll
            for (int nt = 0; nt < 8; nt++) {
                float p0 = __expf(s[nt][2 * e]     - mnew);
                float p1 = __expf(s[nt][2 * e + 1] - mnew);
                rsum += p0 + p1;
                __half2 hp = __floats2half2_rn(p0, p1);
                ph[nt][e] = *(uint32_t*)&hp;
            }
            rsum += __shfl_xor_sync(0xffffffffu, rsum, 1);
            rsum += __shfl_xor_sync(0xffffffffu, rsum, 2);
            l_i[e] = l_i[e] * corr + rsum;
#pragma unroll
            for (int nt = 0; nt < 16; nt++) {
                o[nt][2 * e]     *= corr;
                o[nt][2 * e + 1] *= corr;
            }
        }

        // ---- O += P @ V (fp16 mma; P fragments already in registers) ----
#pragma unroll
        for (int ks = 0; ks < 4; ks++) {
            uint32_t a[4] = { ph[2 * ks][0], ph[2 * ks][1],
                              ph[2 * ks + 1][0], ph[2 * ks + 1][1] };
#pragma unroll
            for (int nt = 0; nt < 16; nt++) {
                int vb = (nt * 8 + gid) * AVS + ks * 8 + tig;
                mma_fp16(o[nt], a, Vw[vb], Vw[vb + 4]);
            }
        }
    }

    // ---- epilogue: normalize & store (b,t,h,d) ----
    float* obase = Oc + (((size_t)b * TT + qi0 + warp * 16) * NH + h) * HD;
    float inv0 = 1.0f / l_i[0];
    float inv1 = 1.0f / l_i[1];
#pragma unroll
    for (int nt = 0; nt < 16; nt++) {
        float2 v0 = { o[nt][0] * inv0, o[nt][1] * inv0 };
        float2 v1 = { o[nt][2] * inv1, o[nt][3] * inv1 };
        *(float2*)&obase[(size_t)gid * QN + nt * 8 + 2 * tig]       = v0;
        *(float2*)&obase[(size_t)(gid + 8) * QN + nt * 8 + 2 * tig] = v1;
    }
}

// ---------------------------------------------------------------------------
// Launch
// ---------------------------------------------------------------------------
extern "C" void kernel_launch(void* const* d_in, const int* in_sizes, int n_in,
                              void* d_out, int out_size)
{
    const float* x    = (const float*)d_in[0];
    const float* wq   = (const float*)d_in[1];
    const float* wk   = (const float*)d_in[2];
    const float* wv   = (const float*)d_in[3];
    const float* wo   = (const float*)d_in[4];
    const float* cosp = (const float*)d_in[5];
    const float* sinp = (const float*)d_in[6];
    float* out = (float*)d_out;

    float *qp, *kp, *vp, *ap, *wqT, *wkT, *wvT, *woT;
    cudaGetSymbolAddress((void**)&qp,  g_q);
    cudaGetSymbolAddress((void**)&kp,  g_k);
    cudaGetSymbolAddress((void**)&vp,  g_v);
    cudaGetSymbolAddress((void**)&ap,  g_attn);
    cudaGetSymbolAddress((void**)&wqT, g_wqT);
    cudaGetSymbolAddress((void**)&wkT, g_wkT);
    cudaGetSymbolAddress((void**)&wvT, g_wvT);
    cudaGetSymbolAddress((void**)&woT, g_woT);

    cudaFuncSetAttribute(attn_mma_kernel,
                         cudaFuncAttributeMaxDynamicSharedMemorySize,
                         ATTN_SMEM_BYTES);

    // Transpose weights to [N][K]
    dim3 tb(32, 8);
    transpose_kernel<<<dim3(QN / 32, DM / 32), tb>>>(wq, wqT, DM, QN);
    transpose_kernel<<<dim3(KN / 32, DM / 32), tb>>>(wk, wkT, DM, KN);
    transpose_kernel<<<dim3(KN / 32, DM / 32), tb>>>(wv, wvT, DM, KN);
    transpose_kernel<<<dim3(QN / 32, DM / 32), tb>>>(wo, woT, DM, DM);

    // QKV projections (tf32 tensor cores)
    gemm_tf32<<<dim3(QN / GBN, MTOT / GBM), 256>>>(x, wqT, qp, MTOT, QN, DM);
    gemm_tf32_kv<<<dim3(KN / GBN, MTOT / GBM, 2), 256>>>(
        x, wkT, wvT, kp, vp, MTOT, KN, DM);

    // RoPE (in-place)
    {
        int tq = BB * TT * NH * HALF;
        rope_kernel<<<(tq + 255) / 256, 256>>>(qp, cosp, sinp, NH);
        int tk = BB * TT * NKV * HALF;
        rope_kernel<<<(tk + 255) / 256, 256>>>(kp, cosp, sinp, NKV);
    }

    // Flash attention (tensor cores)
    attn_mma_kernel<<<dim3(TT / 128, NH, BB), 256, ATTN_SMEM_BYTES>>>(
        qp, kp, vp, ap);

    // Output projection (tf32 tensor cores)
    gemm_tf32<<<dim3(QN / GBN, MTOT / GBM), 256>>>(ap, woT, out, MTOT, QN, DM);
}

// round 8
// speedup vs baseline: 3.3759x; 1.1056x over previous
#include <cuda_runtime.h>
#include <cuda_fp16.h>
#include <math.h>
#include <stdint.h>

// Problem constants
#define BB 2
#define TT 2048
#define DM 2048
#define NH 16
#define HD 128
#define NKV 4
#define NREP 4
#define HALF 64
#define MTOT (BB*TT)      // 4096
#define QN (NH*HD)        // 2048
#define KN (NKV*HD)       // 512

// Scratch (device globals: no allocations allowed)
__device__ float    g_q[MTOT * QN];     // 32 MB (rope -> tf32 bits)
__device__ float    g_k[MTOT * KN];     //  8 MB (rope -> tf32 bits)
__device__ float    g_v[MTOT * KN];     //  8 MB fp32
__device__ float    g_attn[MTOT * QN];  // 32 MB (tf32 bits)
__device__ uint32_t g_x32[MTOT * DM];   // 32 MB x as tf32
__device__ uint32_t g_wqT[DM * QN];     // 16 MB transposed tf32 weights
__device__ uint32_t g_wkT[DM * KN];     //  4 MB
__device__ uint32_t g_wvT[DM * KN];     //  4 MB
__device__ uint32_t g_woT[DM * DM];     // 16 MB
__device__ __half   g_vt[(size_t)BB * NKV * HD * TT];  // 4 MB V^T fp16 (b,kv,d,t)

__device__ __forceinline__ uint32_t f2tf32(float x) {
    uint32_t u;
    asm("cvt.rna.tf32.f32 %0, %1;" : "=r"(u) : "f"(x));
    return u;
}

// ---------------------------------------------------------------------------
// Elementwise fp32 -> tf32 bits
// ---------------------------------------------------------------------------
__global__ void cvt_tf32_kernel(const float4* __restrict__ src,
                                uint4* __restrict__ dst, int n4)
{
    int i = blockIdx.x * blockDim.x + threadIdx.x;
    if (i >= n4) return;
    float4 v = src[i];
    dst[i] = make_uint4(f2tf32(v.x), f2tf32(v.y), f2tf32(v.z), f2tf32(v.w));
}

// ---------------------------------------------------------------------------
// Weight transpose + tf32 convert: src [R][C] fp32 -> dst [C][R] tf32 bits
// ---------------------------------------------------------------------------
__global__ void transpose_kernel(const float* __restrict__ src,
                                 uint32_t* __restrict__ dst, int R, int C)
{
    __shared__ float t[32][33];
    int c0 = blockIdx.x * 32, r0 = blockIdx.y * 32;
    int x = threadIdx.x, y = threadIdx.y;   // block (32, 8)
#pragma unroll
    for (int i = 0; i < 32; i += 8)
        t[y + i][x] = src[(size_t)(r0 + y + i) * C + c0 + x];
    __syncthreads();
#pragma unroll
    for (int i = 0; i < 32; i += 8)
        dst[(size_t)(c0 + y + i) * R + r0 + x] = f2tf32(t[x][y + i]);
}

// ---------------------------------------------------------------------------
// V fp32 (b,t,kv,d) -> V^T fp16 (b,kv,d,t)
// ---------------------------------------------------------------------------
__global__ void v_to_half_t_kernel(const float* __restrict__ v,
                                   __half* __restrict__ vt)
{
    __shared__ float t[32][33];
    int t0 = blockIdx.x * 32;
    int d0 = blockIdx.y * 32;
    int bk = blockIdx.z;                    // b*NKV + kv
    int b = bk >> 2, kv = bk & 3;
    int x = threadIdx.x, y = threadIdx.y;   // (32, 8)
    const float* src = v + ((size_t)b * TT) * KN + kv * HD;
#pragma unroll
    for (int i = 0; i < 32; i += 8)
        t[y + i][x] = src[(size_t)(t0 + y + i) * KN + d0 + x];
    __syncthreads();
    __half* dst = vt + ((size_t)bk * HD + d0) * TT + t0;
#pragma unroll
    for (int i = 0; i < 32; i += 8)
        dst[(size_t)(y + i) * TT + x] = __float2half(t[x][y + i]);
}

// ---------------------------------------------------------------------------
// MMA helpers
// ---------------------------------------------------------------------------
__device__ __forceinline__ void mma_tf32(float* d, const uint32_t* a,
                                         const uint32_t* b) {
    asm volatile(
        "mma.sync.aligned.m16n8k8.row.col.f32.tf32.tf32.f32 "
        "{%0,%1,%2,%3}, {%4,%5,%6,%7}, {%8,%9}, {%0,%1,%2,%3};\n"
        : "+f"(d[0]), "+f"(d[1]), "+f"(d[2]), "+f"(d[3])
        : "r"(a[0]), "r"(a[1]), "r"(a[2]), "r"(a[3]),
          "r"(b[0]), "r"(b[1]));
}

__device__ __forceinline__ void mma_fp16(float* d, const uint32_t* a,
                                         uint32_t b0, uint32_t b1) {
    asm volatile(
        "mma.sync.aligned.m16n8k16.row.col.f32.f16.f16.f32 "
        "{%0,%1,%2,%3}, {%4,%5,%6,%7}, {%8,%9}, {%0,%1,%2,%3};\n"
        : "+f"(d[0]), "+f"(d[1]), "+f"(d[2]), "+f"(d[3])
        : "r"(a[0]), "r"(a[1]), "r"(a[2]), "r"(a[3]),
          "r"(b0), "r"(b1));
}

// ---------------------------------------------------------------------------
// TF32 tensor-core GEMM, inputs pre-converted to tf32 bits.
// C[M,N] = A[M,K] @ B[K,N], B supplied transposed as Bt[N][K].
// CTA tile 256x128, BK=16, 8 warps (4x2), warp tile 64x64, m16n8k8.
// ---------------------------------------------------------------------------
#define GBM 256
#define GBN 128
#define GBK 16

__device__ __forceinline__ void gemm_body(
    const uint32_t* __restrict__ A, const uint32_t* __restrict__ Bt,
    float* __restrict__ C, int M, int N, int K)
{
    __shared__ __align__(16) uint32_t As[GBM * GBK];
    __shared__ __align__(16) uint32_t Bs[GBN * GBK];

    const int tid  = threadIdx.x;
    const int lane = tid & 31;
    const int warp = tid >> 5;
    const int gid  = lane >> 2;
    const int tig  = lane & 3;
    const int wy   = warp >> 1;
    const int wx   = warp & 1;
    const int m0   = blockIdx.y * GBM;
    const int n0   = blockIdx.x * GBN;

    const int c4    = tid & 3;
    const int rbase = tid >> 2;
    const int ksS   = c4 >> 1;
    const int khS   = c4 & 1;

    const uint32_t* Ag = A  + (size_t)(m0 + rbase) * K + c4 * 4;
    const uint32_t* Bg = Bt + (size_t)(n0 + rbase) * K + c4 * 4;

    float acc[4][8][4];
#pragma unroll
    for (int mt = 0; mt < 4; mt++)
#pragma unroll
        for (int nt = 0; nt < 8; nt++)
#pragma unroll
            for (int r = 0; r < 4; r++) acc[mt][nt][r] = 0.0f;

    uint4 pa[4], pb[2];
    const int NC = K / GBK;

#pragma unroll
    for (int i = 0; i < 4; i++)
        pa[i] = *(const uint4*)&Ag[(size_t)(64 * i) * K];
#pragma unroll
    for (int i = 0; i < 2; i++)
        pb[i] = *(const uint4*)&Bg[(size_t)(64 * i) * K];

    {
#pragma unroll
        for (int i = 0; i < 4; i++) {
            int r  = rbase + 64 * i;
            int Mi = r >> 4, g = r & 7, rh = (r >> 3) & 1;
            int base = ((Mi * 2 + ksS) * 32 + g * 4);
            int roff = rh + 2 * khS;
            uint32_t e[4] = {pa[i].x, pa[i].y, pa[i].z, pa[i].w};
#pragma unroll
            for (int jj = 0; jj < 4; jj++) {
                int j = (jj + c4 + g) & 3;
                As[(base + j) * 4 + roff] = e[j];
            }
        }
#pragma unroll
        for (int i = 0; i < 2; i++) {
            int r  = rbase + 64 * i;
            int Ni = r >> 3, g = r & 7;
            int base = ((Ni * 2 + ksS) * 32 + g * 4);
            uint32_t e[4] = {pb[i].x, pb[i].y, pb[i].z, pb[i].w};
#pragma unroll
            for (int jj = 0; jj < 4; jj++) {
                int j = (jj + c4 + g) & 3;
                Bs[(base + j) * 2 + khS] = e[j];
            }
        }
    }
    __syncthreads();

    for (int kc = 0; kc < NC; kc++) {
        if (kc + 1 < NC) {
            size_t koff = (size_t)(kc + 1) * GBK;
#pragma unroll
            for (int i = 0; i < 4; i++)
                pa[i] = *(const uint4*)&Ag[(size_t)(64 * i) * K + koff];
#pragma unroll
            for (int i = 0; i < 2; i++)
                pb[i] = *(const uint4*)&Bg[(size_t)(64 * i) * K + koff];
        }

#pragma unroll
        for (int ks = 0; ks < 2; ks++) {
            uint32_t a[4][4], b[8][2];
#pragma unroll
            for (int mt = 0; mt < 4; mt++) {
                int Mi = wy * 4 + mt;
                uint4 v = *(const uint4*)&As[((Mi * 2 + ks) * 32 + lane) * 4];
                a[mt][0] = v.x; a[mt][1] = v.y; a[mt][2] = v.z; a[mt][3] = v.w;
            }
#pragma unroll
            for (int nt = 0; nt < 8; nt++) {
                int Ni = wx * 8 + nt;
                uint2 v = *(const uint2*)&Bs[((Ni * 2 + ks) * 32 + lane) * 2];
                b[nt][0] = v.x; b[nt][1] = v.y;
            }
#pragma unroll
            for (int mt = 0; mt < 4; mt++)
#pragma unroll
                for (int nt = 0; nt < 8; nt++)
                    mma_tf32(acc[mt][nt], a[mt], b[nt]);
        }

        if (kc + 1 < NC) {
            __syncthreads();
#pragma unroll
            for (int i = 0; i < 4; i++) {
                int r  = rbase + 64 * i;
                int Mi = r >> 4, g = r & 7, rh = (r >> 3) & 1;
                int base = ((Mi * 2 + ksS) * 32 + g * 4);
                int roff = rh + 2 * khS;
                uint32_t e[4] = {pa[i].x, pa[i].y, pa[i].z, pa[i].w};
#pragma unroll
                for (int jj = 0; jj < 4; jj++) {
                    int j = (jj + c4 + g) & 3;
                    As[(base + j) * 4 + roff] = e[j];
                }
            }
#pragma unroll
            for (int i = 0; i < 2; i++) {
                int r  = rbase + 64 * i;
                int Ni = r >> 3, g = r & 7;
                int base = ((Ni * 2 + ksS) * 32 + g * 4);
                uint32_t e[4] = {pb[i].x, pb[i].y, pb[i].z, pb[i].w};
#pragma unroll
                for (int jj = 0; jj < 4; jj++) {
                    int j = (jj + c4 + g) & 3;
                    Bs[(base + j) * 2 + khS] = e[j];
                }
            }
            __syncthreads();
        }
    }

#pragma unroll
    for (int mt = 0; mt < 4; mt++) {
        int row = m0 + wy * 64 + mt * 16 + gid;
#pragma unroll
        for (int nt = 0; nt < 8; nt++) {
            int col = n0 + wx * 64 + nt * 8 + tig * 2;
            float2 lo = {acc[mt][nt][0], acc[mt][nt][1]};
            float2 hi = {acc[mt][nt][2], acc[mt][nt][3]};
            *(float2*)&C[(size_t)row * N + col]       = lo;
            *(float2*)&C[(size_t)(row + 8) * N + col] = hi;
        }
    }
}

__global__ __launch_bounds__(256, 1) void gemm_tf32(
    const uint32_t* __restrict__ A, const uint32_t* __restrict__ Bt,
    float* __restrict__ C, int M, int N, int K)
{
    gemm_body(A, Bt, C, M, N, K);
}

__global__ __launch_bounds__(256, 1) void gemm_tf32_kv(
    const uint32_t* __restrict__ A,
    const uint32_t* __restrict__ BtK, const uint32_t* __restrict__ BtV,
    float* __restrict__ Ck, float* __restrict__ Cv, int M, int N, int K)
{
    const uint32_t* Bt = blockIdx.z ? BtV : BtK;
    float* C = blockIdx.z ? Cv : Ck;
    gemm_body(A, Bt, C, M, N, K);
}

// ---------------------------------------------------------------------------
// RoPE in-place, output written as tf32 bits, optional extra scale (for Q).
// ---------------------------------------------------------------------------
__global__ void rope_tf32_kernel(float* __restrict__ q,
                                 const float* __restrict__ cosp,
                                 const float* __restrict__ sinp,
                                 int heads, float sc)
{
    int idx = blockIdx.x * blockDim.x + threadIdx.x;
    int total = BB * TT * heads * HALF;
    if (idx >= total) return;
    int i = idx % HALF;
    int h = (idx / HALF) % heads;
    int t = (idx / (HALF * heads)) % TT;
    int b = idx / (HALF * heads * TT);
    float c = cosp[t * HALF + i];
    float s = sinp[t * HALF + i];
    float* p = q + ((((size_t)b * TT + t) * heads + h) * HD);
    float x1 = p[i];
    float x2 = p[i + HALF];
    p[i]        = __uint_as_float(f2tf32((x1 * c - x2 * s) * sc));
    p[i + HALF] = __uint_as_float(f2tf32((x2 * c + x1 * s) * sc));
}

// ---------------------------------------------------------------------------
// Tensor-core causal GQA flash attention — all staging is CVT-free.
// Q/K arrive as tf32 bits (Q pre-scaled by rope), V^T arrives as fp16.
// CTA: 128 q rows, key tiles of 64, 8 warps, warp owns 16 rows.
// ---------------------------------------------------------------------------
#define AQS 132
#define AVS 36
#define ATTN_SMEM_BYTES ((128*AQS + 64*AQS + 128*AVS) * 4)   // 119808

__global__ __launch_bounds__(256, 1) void attn_mma_kernel(
    const uint32_t* __restrict__ Q, const uint32_t* __restrict__ Kc,
    const __half* __restrict__ Vt, float* __restrict__ Oc)
{
    extern __shared__ uint32_t smw[];
    uint32_t* Qs = smw;                  // [128][132] tf32 bits
    uint32_t* Ks = Qs + 128 * AQS;       // [64][132] tf32 bits
    uint32_t* Vw = Ks + 64 * AQS;        // [128][36] half2 (V^T key-pairs)

    const int tid  = threadIdx.x;
    const int lane = tid & 31;
    const int warp = tid >> 5;
    const int gid  = lane >> 2;
    const int tig  = lane & 3;
    const int qt   = (gridDim.x - 1) - blockIdx.x;   // long CTAs first
    const int h    = blockIdx.y;
    const int b    = blockIdx.z;
    const int kvh  = h >> 2;
    const int qi0  = qt * 128;

    // ---- stage Q (pure copy; already scaled tf32 bits) ----
    const uint32_t* qbase = Q + (((size_t)b * TT + qi0) * NH + h) * HD;
#pragma unroll
    for (int i = 0; i < 16; i++) {
        int idx = tid + i * 256;
        int r = idx >> 5, d4 = idx & 31;
        *(uint4*)&Qs[r * AQS + d4 * 4] =
            *(const uint4*)&qbase[(size_t)r * QN + d4 * 4];
    }

    float m_i[2] = {-1e30f, -1e30f};
    float l_i[2] = {0.0f, 0.0f};
    float o[16][4];
#pragma unroll
    for (int nt = 0; nt < 16; nt++)
#pragma unroll
        for (int r = 0; r < 4; r++) o[nt][r] = 0.0f;

    const int arow = warp * 16 + gid;
    const int ntiles = qi0 / 64 + 2;
    const __half* vth = Vt + ((size_t)(b * NKV + kvh) * HD) * TT;

    for (int kt = 0; kt < ntiles; kt++) {
        const int kj0 = kt * 64;
        __syncthreads();

        // ---- stage K (pure copy) ----
        const uint32_t* kbase = Kc + (((size_t)b * TT + kj0) * NKV + kvh) * HD;
#pragma unroll
        for (int i = 0; i < 8; i++) {
            int idx = tid + i * 256;
            int r = idx >> 5, d4 = idx & 31;
            *(uint4*)&Ks[r * AQS + d4 * 4] =
                *(const uint4*)&kbase[(size_t)r * KN + d4 * 4];
        }
        // ---- stage V^T (pure half2 copy) ----
#pragma unroll
        for (int i = 0; i < 16; i++) {
            int idx = i * 256 + tid;               // 0..4095
            int kp = idx & 31, d = idx >> 5;
            Vw[d * AVS + kp] =
                *(const uint32_t*)&vth[(size_t)d * TT + kj0 + 2 * kp];
        }
        __syncthreads();

        // ---- S = Q K^T (tf32 mma, warp tile 16x64) ----
        float s[8][4];
#pragma unroll
        for (int nt = 0; nt < 8; nt++)
#pragma unroll
            for (int r = 0; r < 4; r++) s[nt][r] = 0.0f;

#pragma unroll
        for (int ks = 0; ks < 16; ks++) {
            uint32_t a[4];
            int ab = arow * AQS + ks * 8 + tig;
            a[0] = Qs[ab];
            a[1] = Qs[ab + 8 * AQS];
            a[2] = Qs[ab + 4];
            a[3] = Qs[ab + 8 * AQS + 4];
#pragma unroll
            for (int nt = 0; nt < 8; nt++) {
                int kb = (nt * 8 + gid) * AQS + ks * 8 + tig;
                uint32_t bb[2] = { Ks[kb], Ks[kb + 4] };
                mma_tf32(s[nt], a, bb);
            }
        }

        // ---- causal mask ----
        if (kt >= ntiles - 2) {
#pragma unroll
            for (int nt = 0; nt < 8; nt++)
#pragma unroll
                for (int r = 0; r < 4; r++) {
                    int row = qi0 + warp * 16 + gid + (r >> 1) * 8;
                    int col = kj0 + nt * 8 + 2 * tig + (r & 1);
                    if (col > row) s[nt][r] = -1e30f;
                }
        }

        // ---- online softmax ----
        uint32_t ph[8][2];
#pragma unroll
        for (int e = 0; e < 2; e++) {
            float mx = -1e30f;
#pragma unroll
            for (int nt = 0; nt < 8; nt++)
                mx = fmaxf(mx, fmaxf(s[nt][2 * e], s[nt][2 * e + 1]));
            mx = fmaxf(mx, __shfl_xor_sync(0xffffffffu, mx, 1));
            mx = fmaxf(mx, __shfl_xor_sync(0xffffffffu, mx, 2));
            float mnew = fmaxf(m_i[e], mx);
            float corr = __expf(m_i[e] - mnew);
            m_i[e] = mnew;
            float rsum = 0.0f;
#pragma unroll
            for (int nt = 0; nt < 8; nt++) {
                float p0 = __expf(s[nt][2 * e]     - mnew);
                float p1 = __expf(s[nt][2 * e + 1] - mnew);
                rsum += p0 + p1;
                __half2 hp = __floats2half2_rn(p0, p1);
                ph[nt][e] = *(uint32_t*)&hp;
            }
            rsum += __shfl_xor_sync(0xffffffffu, rsum, 1);
            rsum += __shfl_xor_sync(0xffffffffu, rsum, 2);
            l_i[e] = l_i[e] * corr + rsum;
#pragma unroll
            for (int nt = 0; nt < 16; nt++) {
                o[nt][2 * e]     *= corr;
                o[nt][2 * e + 1] *= corr;
            }
        }

        // ---- O += P @ V (fp16 mma) ----
#pragma unroll
        for (int ks = 0; ks < 4; ks++) {
            uint32_t a[4] = { ph[2 * ks][0], ph[2 * ks][1],
                              ph[2 * ks + 1][0], ph[2 * ks + 1][1] };
#pragma unroll
            for (int nt = 0; nt < 16; nt++) {
                int vb = (nt * 8 + gid) * AVS + ks * 8 + tig;
                mma_fp16(o[nt], a, Vw[vb], Vw[vb + 4]);
            }
        }
    }

    // ---- epilogue: normalize, write tf32 bits (feeds O-proj GEMM) ----
    float* obase = Oc + (((size_t)b * TT + qi0 + warp * 16) * NH + h) * HD;
    float inv0 = 1.0f / l_i[0];
    float inv1 = 1.0f / l_i[1];
#pragma unroll
    for (int nt = 0; nt < 16; nt++) {
        float2 v0 = { __uint_as_float(f2tf32(o[nt][0] * inv0)),
                      __uint_as_float(f2tf32(o[nt][1] * inv0)) };
        float2 v1 = { __uint_as_float(f2tf32(o[nt][2] * inv1)),
                      __uint_as_float(f2tf32(o[nt][3] * inv1)) };
        *(float2*)&obase[(size_t)gid * QN + nt * 8 + 2 * tig]       = v0;
        *(float2*)&obase[(size_t)(gid + 8) * QN + nt * 8 + 2 * tig] = v1;
    }
}

// ---------------------------------------------------------------------------
// Launch
// ---------------------------------------------------------------------------
extern "C" void kernel_launch(void* const* d_in, const int* in_sizes, int n_in,
                              void* d_out, int out_size)
{
    const float* x    = (const float*)d_in[0];
    const float* wq   = (const float*)d_in[1];
    const float* wk   = (const float*)d_in[2];
    const float* wv   = (const float*)d_in[3];
    const float* wo   = (const float*)d_in[4];
    const float* cosp = (const float*)d_in[5];
    const float* sinp = (const float*)d_in[6];
    float* out = (float*)d_out;

    float *qp, *kp, *vp, *ap;
    uint32_t *x32, *wqT, *wkT, *wvT, *woT;
    __half* vt;
    cudaGetSymbolAddress((void**)&qp,  g_q);
    cudaGetSymbolAddress((void**)&kp,  g_k);
    cudaGetSymbolAddress((void**)&vp,  g_v);
    cudaGetSymbolAddress((void**)&ap,  g_attn);
    cudaGetSymbolAddress((void**)&x32, g_x32);
    cudaGetSymbolAddress((void**)&wqT, g_wqT);
    cudaGetSymbolAddress((void**)&wkT, g_wkT);
    cudaGetSymbolAddress((void**)&wvT, g_wvT);
    cudaGetSymbolAddress((void**)&woT, g_woT);
    cudaGetSymbolAddress((void**)&vt,  g_vt);

    cudaFuncSetAttribute(attn_mma_kernel,
                         cudaFuncAttributeMaxDynamicSharedMemorySize,
                         ATTN_SMEM_BYTES);

    const float scale = 0.08838834764831845f;  // 1/sqrt(128)

    // x -> tf32 once
    {
        int n4 = MTOT * DM / 4;
        cvt_tf32_kernel<<<(n4 + 255) / 256, 256>>>(
            (const float4*)x, (uint4*)x32, n4);
    }

    // Transpose+convert weights to [N][K] tf32
    dim3 tb(32, 8);
    transpose_kernel<<<dim3(QN / 32, DM / 32), tb>>>(wq, wqT, DM, QN);
    transpose_kernel<<<dim3(KN / 32, DM / 32), tb>>>(wk, wkT, DM, KN);
    transpose_kernel<<<dim3(KN / 32, DM / 32), tb>>>(wv, wvT, DM, KN);
    transpose_kernel<<<dim3(QN / 32, DM / 32), tb>>>(wo, woT, DM, DM);

    // QKV projections (tf32 tensor cores)
    gemm_tf32<<<dim3(QN / GBN, MTOT / GBM), 256>>>(x32, wqT, qp, MTOT, QN, DM);
    gemm_tf32_kv<<<dim3(KN / GBN, MTOT / GBM, 2), 256>>>(
        x32, wkT, wvT, kp, vp, MTOT, KN, DM);

    // RoPE -> tf32 bits (Q gets 1/sqrt(d) folded in)
    {
        int tq = BB * TT * NH * HALF;
        rope_tf32_kernel<<<(tq + 255) / 256, 256>>>(qp, cosp, sinp, NH, scale);
        int tk = BB * TT * NKV * HALF;
        rope_tf32_kernel<<<(tk + 255) / 256, 256>>>(kp, cosp, sinp, NKV, 1.0f);
    }

    // V -> fp16 transposed (b,kv,d,t)
    v_to_half_t_kernel<<<dim3(TT / 32, HD / 32, BB * NKV), tb>>>(vp, vt);

    // Flash attention (tensor cores, CVT-free staging)
    attn_mma_kernel<<<dim3(TT / 128, NH, BB), 256, ATTN_SMEM_BYTES>>>(
        (const uint32_t*)qp, (const uint32_t*)kp, vt, ap);

    // Output projection (tf32 tensor cores)
    gemm_tf32<<<dim3(QN / GBN, MTOT / GBM), 256>>>(
        (const uint32_t*)ap, woT, out, MTOT, QN, DM);
}

// round 14
// speedup vs baseline: 5.8255x; 1.7256x over previous
#include <cuda_runtime.h>
#include <cuda_fp16.h>
#include <math.h>
#include <stdint.h>

// Problem constants
#define BB 2
#define TT 2048
#define DM 2048
#define NH 16
#define HD 128
#define NKV 4
#define NREP 4
#define HALF 64
#define MTOT (BB*TT)      // 4096
#define QN (NH*HD)        // 2048
#define KN (NKV*HD)       // 512

// Scratch (device globals: no allocations allowed)
__device__ float  g_q[MTOT * QN];      // 32 MB  Q proj out (fp32)
__device__ float  g_k[MTOT * KN];      //  8 MB  K proj out (fp32)
__device__ float  g_v[MTOT * KN];      //  8 MB  V proj out (fp32)
__device__ __half g_qh[MTOT * QN];     // 16 MB  rope(Q) fp16
__device__ __half g_kh[MTOT * KN];     //  4 MB  rope(K) fp16
__device__ __half g_ah[MTOT * QN];     // 16 MB  attention out fp16
__device__ __half g_xh[MTOT * DM];     // 16 MB  x as fp16
__device__ __half g_wqT[DM * QN];      //  8 MB  transposed fp16 weights [N][K]
__device__ __half g_wkT[DM * KN];      //  2 MB
__device__ __half g_wvT[DM * KN];      //  2 MB
__device__ __half g_woT[DM * DM];      //  8 MB
__device__ __half g_vt[(size_t)BB * NKV * HD * TT];  // 4 MB V^T fp16 (b,kv,d,t)

// ---------------------------------------------------------------------------
// MMA helpers (fp16, f32 accumulate)
// ---------------------------------------------------------------------------
__device__ __forceinline__ void mma_fp16(float* d, const uint32_t* a,
                                         uint32_t b0, uint32_t b1) {
    asm volatile(
        "mma.sync.aligned.m16n8k16.row.col.f32.f16.f16.f32 "
        "{%0,%1,%2,%3}, {%4,%5,%6,%7}, {%8,%9}, {%0,%1,%2,%3};\n"
        : "+f"(d[0]), "+f"(d[1]), "+f"(d[2]), "+f"(d[3])
        : "r"(a[0]), "r"(a[1]), "r"(a[2]), "r"(a[3]),
          "r"(b0), "r"(b1));
}

// ---------------------------------------------------------------------------
// Elementwise fp32 -> fp16
// ---------------------------------------------------------------------------
__global__ void cvt_fp16_kernel(const float4* __restrict__ src,
                                uint2* __restrict__ dst, int n4)
{
    int i = blockIdx.x * blockDim.x + threadIdx.x;
    if (i >= n4) return;
    float4 v = src[i];
    __half2 lo = __floats2half2_rn(v.x, v.y);
    __half2 hi = __floats2half2_rn(v.z, v.w);
    dst[i] = make_uint2(*(uint32_t*)&lo, *(uint32_t*)&hi);
}

// ---------------------------------------------------------------------------
// Weight transpose + fp16 convert: src [R][C] fp32 -> dst [C][R] fp16
// ---------------------------------------------------------------------------
__global__ void transpose_kernel(const float* __restrict__ src,
                                 __half* __restrict__ dst, int R, int C)
{
    __shared__ float t[32][33];
    int c0 = blockIdx.x * 32, r0 = blockIdx.y * 32;
    int x = threadIdx.x, y = threadIdx.y;   // block (32, 8)
#pragma unroll
    for (int i = 0; i < 32; i += 8)
        t[y + i][x] = src[(size_t)(r0 + y + i) * C + c0 + x];
    __syncthreads();
#pragma unroll
    for (int i = 0; i < 32; i += 8)
        dst[(size_t)(c0 + y + i) * R + r0 + x] = __float2half(t[x][y + i]);
}

// ---------------------------------------------------------------------------
// V fp32 (b,t,kv,d) -> V^T fp16 (b,kv,d,t)
// ---------------------------------------------------------------------------
__global__ void v_to_half_t_kernel(const float* __restrict__ v,
                                   __half* __restrict__ vt)
{
    __shared__ float t[32][33];
    int t0 = blockIdx.x * 32;
    int d0 = blockIdx.y * 32;
    int bk = blockIdx.z;
    int b = bk >> 2, kv = bk & 3;
    int x = threadIdx.x, y = threadIdx.y;   // (32, 8)
    const float* src = v + ((size_t)b * TT) * KN + kv * HD;
#pragma unroll
    for (int i = 0; i < 32; i += 8)
        t[y + i][x] = src[(size_t)(t0 + y + i) * KN + d0 + x];
    __syncthreads();
    __half* dst = vt + ((size_t)bk * HD + d0) * TT + t0;
#pragma unroll
    for (int i = 0; i < 32; i += 8)
        dst[(size_t)(y + i) * TT + x] = __float2half(t[x][y + i]);
}

// ---------------------------------------------------------------------------
// FP16 tensor-core GEMM: C[M,N] = A[M,K] @ B[K,N], fp32 out.
// A and Bt supplied as fp16 viewed as half2 WORDS; Kw = K/2 is the word count.
// Word-level fragment layout of m16n8k16.f16 == m16n8k8.tf32, so this is the
// validated R8 body with the MMA swapped. CTA tile 256x128 (elements),
// chunk = 16 words = 32 k-elements, 8 warps (4x2), warp tile 64x64.
// ---------------------------------------------------------------------------
#define GBM 256
#define GBN 128
#define GBKW 16   // words per chunk (= 32 halves)

__device__ __forceinline__ void gemm_body(
    const uint32_t* __restrict__ A, const uint32_t* __restrict__ Bt,
    float* __restrict__ C, int M, int N, int Kw)
{
    __shared__ __align__(16) uint32_t As[GBM * GBKW];
    __shared__ __align__(16) uint32_t Bs[GBN * GBKW];

    const int tid  = threadIdx.x;
    const int lane = tid & 31;
    const int warp = tid >> 5;
    const int gid  = lane >> 2;
    const int tig  = lane & 3;
    const int wy   = warp >> 1;
    const int wx   = warp & 1;
    const int m0   = blockIdx.y * GBM;
    const int n0   = blockIdx.x * GBN;

    const int c4    = tid & 3;
    const int rbase = tid >> 2;
    const int ksS   = c4 >> 1;
    const int khS   = c4 & 1;

    const uint32_t* Ag = A  + (size_t)(m0 + rbase) * Kw + c4 * 4;
    const uint32_t* Bg = Bt + (size_t)(n0 + rbase) * Kw + c4 * 4;

    float acc[4][8][4];
#pragma unroll
    for (int mt = 0; mt < 4; mt++)
#pragma unroll
        for (int nt = 0; nt < 8; nt++)
#pragma unroll
            for (int r = 0; r < 4; r++) acc[mt][nt][r] = 0.0f;

    uint4 pa[4], pb[2];
    const int NC = Kw / GBKW;

#pragma unroll
    for (int i = 0; i < 4; i++)
        pa[i] = *(const uint4*)&Ag[(size_t)(64 * i) * Kw];
#pragma unroll
    for (int i = 0; i < 2; i++)
        pb[i] = *(const uint4*)&Bg[(size_t)(64 * i) * Kw];

    {
#pragma unroll
        for (int i = 0; i < 4; i++) {
            int r  = rbase + 64 * i;
            int Mi = r >> 4, g = r & 7, rh = (r >> 3) & 1;
            int base = ((Mi * 2 + ksS) * 32 + g * 4);
            int roff = rh + 2 * khS;
            uint32_t e[4] = {pa[i].x, pa[i].y, pa[i].z, pa[i].w};
#pragma unroll
            for (int jj = 0; jj < 4; jj++) {
                int j = (jj + c4 + g) & 3;
                As[(base + j) * 4 + roff] = e[j];
            }
        }
#pragma unroll
        for (int i = 0; i < 2; i++) {
            int r  = rbase + 64 * i;
            int Ni = r >> 3, g = r & 7;
            int base = ((Ni * 2 + ksS) * 32 + g * 4);
            uint32_t e[4] = {pb[i].x, pb[i].y, pb[i].z, pb[i].w};
#pragma unroll
            for (int jj = 0; jj < 4; jj++) {
                int j = (jj + c4 + g) & 3;
                Bs[(base + j) * 2 + khS] = e[j];
            }
        }
    }
    __syncthreads();

    for (int kc = 0; kc < NC; kc++) {
        if (kc + 1 < NC) {
            size_t koff = (size_t)(kc + 1) * GBKW;
#pragma unroll
            for (int i = 0; i < 4; i++)
                pa[i] = *(const uint4*)&Ag[(size_t)(64 * i) * Kw + koff];
#pragma unroll
            for (int i = 0; i < 2; i++)
                pb[i] = *(const uint4*)&Bg[(size_t)(64 * i) * Kw + koff];
        }

#pragma unroll
        for (int ks = 0; ks < 2; ks++) {
            uint32_t a[4][4], b[8][2];
#pragma unroll
            for (int mt = 0; mt < 4; mt++) {
                int Mi = wy * 4 + mt;
                uint4 v = *(const uint4*)&As[((Mi * 2 + ks) * 32 + lane) * 4];
                a[mt][0] = v.x; a[mt][1] = v.y; a[mt][2] = v.z; a[mt][3] = v.w;
            }
#pragma unroll
            for (int nt = 0; nt < 8; nt++) {
                int Ni = wx * 8 + nt;
                uint2 v = *(const uint2*)&Bs[((Ni * 2 + ks) * 32 + lane) * 2];
                b[nt][0] = v.x; b[nt][1] = v.y;
            }
#pragma unroll
            for (int mt = 0; mt < 4; mt++)
#pragma unroll
                for (int nt = 0; nt < 8; nt++)
                    mma_fp16(acc[mt][nt], a[mt], b[nt][0], b[nt][1]);
        }

        if (kc + 1 < NC) {
            __syncthreads();
#pragma unroll
            for (int i = 0; i < 4; i++) {
                int r  = rbase + 64 * i;
                int Mi = r >> 4, g = r & 7, rh = (r >> 3) & 1;
                int base = ((Mi * 2 + ksS) * 32 + g * 4);
                int roff = rh + 2 * khS;
                uint32_t e[4] = {pa[i].x, pa[i].y, pa[i].z, pa[i].w};
#pragma unroll
                for (int jj = 0; jj < 4; jj++) {
                    int j = (jj + c4 + g) & 3;
                    As[(base + j) * 4 + roff] = e[j];
                }
            }
#pragma unroll
            for (int i = 0; i < 2; i++) {
                int r  = rbase + 64 * i;
                int Ni = r >> 3, g = r & 7;
                int base = ((Ni * 2 + ksS) * 32 + g * 4);
                uint32_t e[4] = {pb[i].x, pb[i].y, pb[i].z, pb[i].w};
#pragma unroll
                for (int jj = 0; jj < 4; jj++) {
                    int j = (jj + c4 + g) & 3;
                    Bs[(base + j) * 2 + khS] = e[j];
                }
            }
            __syncthreads();
        }
    }

#pragma unroll
    for (int mt = 0; mt < 4; mt++) {
        int row = m0 + wy * 64 + mt * 16 + gid;
#pragma unroll
        for (int nt = 0; nt < 8; nt++) {
            int col = n0 + wx * 64 + nt * 8 + tig * 2;
            float2 lo = {acc[mt][nt][0], acc[mt][nt][1]};
            float2 hi = {acc[mt][nt][2], acc[mt][nt][3]};
            *(float2*)&C[(size_t)row * N + col]       = lo;
            *(float2*)&C[(size_t)(row + 8) * N + col] = hi;
        }
    }
}

__global__ __launch_bounds__(256, 1) void gemm_h(
    const uint32_t* __restrict__ A, const uint32_t* __restrict__ Bt,
    float* __restrict__ C, int M, int N, int Kw)
{
    gemm_body(A, Bt, C, M, N, Kw);
}

__global__ __launch_bounds__(256, 1) void gemm_h_kv(
    const uint32_t* __restrict__ A,
    const uint32_t* __restrict__ BtK, const uint32_t* __restrict__ BtV,
    float* __restrict__ Ck, float* __restrict__ Cv, int M, int N, int Kw)
{
    const uint32_t* Bt = blockIdx.z ? BtV : BtK;
    float* C = blockIdx.z ? Cv : Ck;
    gemm_body(A, Bt, C, M, N, Kw);
}

// ---------------------------------------------------------------------------
// RoPE: read fp32 (b,t,heads,HD), rotate, scale, write fp16.
// ---------------------------------------------------------------------------
__global__ void rope_h_kernel(const float* __restrict__ q,
                              __half* __restrict__ qh,
                              const float* __restrict__ cosp,
                              const float* __restrict__ sinp,
                              int heads, float sc)
{
    int idx = blockIdx.x * blockDim.x + threadIdx.x;
    int total = BB * TT * heads * HALF;
    if (idx >= total) return;
    int i = idx % HALF;
    int h = (idx / HALF) % heads;
    int t = (idx / (HALF * heads)) % TT;
    int b = idx / (HALF * heads * TT);
    float c = cosp[t * HALF + i];
    float s = sinp[t * HALF + i];
    size_t base = (((size_t)b * TT + t) * heads + h) * HD;
    float x1 = q[base + i];
    float x2 = q[base + i + HALF];
    qh[base + i]        = __float2half((x1 * c - x2 * s) * sc);
    qh[base + i + HALF] = __float2half((x2 * c + x1 * s) * sc);
}

// ---------------------------------------------------------------------------
// FP16 tensor-core causal GQA flash attention.
// S = QK^T via m16n8k16.f16 (Q pre-scaled), softmax in registers,
// P in registers as fp16 A-frags, O += P@V via m16n8k16.f16.
// CTA: 128 q rows, key tiles of 64, 8 warps, warp owns 16 rows.
// Smem (words): Qs[128][68] half2, Ks[64][68] half2, Vw[128][36] half2.
// ---------------------------------------------------------------------------
#define AQS 68
#define AVS 36
#define ATTN_SMEM_BYTES ((128*AQS + 64*AQS + 128*AVS) * 4)   // 70656

__global__ __launch_bounds__(256, 1) void attn_mma_kernel(
    const __half* __restrict__ Qh, const __half* __restrict__ Kh,
    const __half* __restrict__ Vt, __half* __restrict__ Oh)
{
    extern __shared__ uint32_t smw[];
    uint32_t* Qs = smw;                  // [128][68] half2 words
    uint32_t* Ks = Qs + 128 * AQS;       // [64][68]
    uint32_t* Vw = Ks + 64 * AQS;        // [128][36] (V^T key-pairs)

    const int tid  = threadIdx.x;
    const int lane = tid & 31;
    const int warp = tid >> 5;
    const int gid  = lane >> 2;
    const int tig  = lane & 3;
    const int qt   = (gridDim.x - 1) - blockIdx.x;   // long CTAs first
    const int h    = blockIdx.y;
    const int b    = blockIdx.z;
    const int kvh  = h >> 2;
    const int qi0  = qt * 128;

    // ---- stage Q (half2 word copy; already scaled) ----
    const uint32_t* qbase = (const uint32_t*)Qh
        + (((size_t)b * TT + qi0) * NH + h) * (HD / 2);
#pragma unroll
    for (int i = 0; i < 8; i++) {
        int idx = tid + i * 256;        // 0..2047
        int r = idx >> 4, d4 = idx & 15;
        *(uint4*)&Qs[r * AQS + d4 * 4] =
            *(const uint4*)&qbase[(size_t)r * (QN / 2) + d4 * 4];
    }

    float m_i[2] = {-1e30f, -1e30f};
    float l_i[2] = {0.0f, 0.0f};
    float o[16][4];
#pragma unroll
    for (int nt = 0; nt < 16; nt++)
#pragma unroll
        for (int r = 0; r < 4; r++) o[nt][r] = 0.0f;

    const int arow = warp * 16 + gid;
    const int ntiles = qi0 / 64 + 2;
    const __half* vth = Vt + ((size_t)(b * NKV + kvh) * HD) * TT;

    for (int kt = 0; kt < ntiles; kt++) {
        const int kj0 = kt * 64;
        __syncthreads();

        // ---- stage K (half2 word copy) ----
        const uint32_t* kbase = (const uint32_t*)Kh
            + (((size_t)b * TT + kj0) * NKV + kvh) * (HD / 2);
#pragma unroll
        for (int i = 0; i < 4; i++) {
            int idx = tid + i * 256;    // 0..1023
            int r = idx >> 4, d4 = idx & 15;
            *(uint4*)&Ks[r * AQS + d4 * 4] =
                *(const uint4*)&kbase[(size_t)r * (KN / 2) + d4 * 4];
        }
        // ---- stage V^T (half2 copy) ----
#pragma unroll
        for (int i = 0; i < 16; i++) {
            int idx = i * 256 + tid;
            int kp = idx & 31, d = idx >> 5;
            Vw[d * AVS + kp] =
                *(const uint32_t*)&vth[(size_t)d * TT + kj0 + 2 * kp];
        }
        __syncthreads();

        // ---- S = Q K^T (fp16 mma, warp tile 16x64, 8 k16-steps) ----
        float s[8][4];
#pragma unroll
        for (int nt = 0; nt < 8; nt++)
#pragma unroll
            for (int r = 0; r < 4; r++) s[nt][r] = 0.0f;

#pragma unroll
        for (int ks = 0; ks < 8; ks++) {
            uint32_t a[4];
            int ab = arow * AQS + ks * 8 + tig;
            a[0] = Qs[ab];
            a[1] = Qs[ab + 8 * AQS];
            a[2] = Qs[ab + 4];
            a[3] = Qs[ab + 8 * AQS + 4];
#pragma unroll
            for (int nt = 0; nt < 8; nt++) {
                int kb = (nt * 8 + gid) * AQS + ks * 8 + tig;
                mma_fp16(s[nt], a, Ks[kb], Ks[kb + 4]);
            }
        }

        // ---- causal mask ----
        if (kt >= ntiles - 2) {
#pragma unroll
            for (int nt = 0; nt < 8; nt++)
#pragma unroll
                for (int r = 0; r < 4; r++) {
                    int row = qi0 + warp * 16 + gid + (r >> 1) * 8;
                    int col = kj0 + nt * 8 + 2 * tig + (r & 1);
                    if (col > row) s[nt][r] = -1e30f;
                }
        }

        // ---- online softmax ----
        uint32_t ph[8][2];
#pragma unroll
        for (int e = 0; e < 2; e++) {
            float mx = -1e30f;
#pragma unroll
            for (int nt = 0; nt < 8; nt++)
                mx = fmaxf(mx, fmaxf(s[nt][2 * e], s[nt][2 * e + 1]));
            mx = fmaxf(mx, __shfl_xor_sync(0xffffffffu, mx, 1));
            mx = fmaxf(mx, __shfl_xor_sync(0xffffffffu, mx, 2));
            float mnew = fmaxf(m_i[e], mx);
            float corr = __expf(m_i[e] - mnew);
            m_i[e] = mnew;
            float rsum = 0.0f;
#pragma unroll
            for (int nt = 0; nt < 8; nt++) {
                float p0 = __expf(s[nt][2 * e]     - mnew);
                float p1 = __expf(s[nt][2 * e + 1] - mnew);
                rsum += p0 + p1;
                __half2 hp = __floats2half2_rn(p0, p1);
                ph[nt][e] = *(uint32_t*)&hp;
            }
            rsum += __shfl_xor_sync(0xffffffffu, rsum, 1);
            rsum += __shfl_xor_sync(0xffffffffu, rsum, 2);
            l_i[e] = l_i[e] * corr + rsum;
#pragma unroll
            for (int nt = 0; nt < 16; nt++) {
                o[nt][2 * e]     *= corr;
                o[nt][2 * e + 1] *= corr;
            }
        }

        // ---- O += P @ V (fp16 mma) ----
#pragma unroll
        for (int ks = 0; ks < 4; ks++) {
            uint32_t a[4] = { ph[2 * ks][0], ph[2 * ks][1],
                              ph[2 * ks + 1][0], ph[2 * ks + 1][1] };
#pragma unroll
            for (int nt = 0; nt < 16; nt++) {
                int vb = (nt * 8 + gid) * AVS + ks * 8 + tig;
                mma_fp16(o[nt], a, Vw[vb], Vw[vb + 4]);
            }
        }
    }

    // ---- epilogue: normalize, write fp16 (feeds O-proj GEMM) ----
    __half* obase = Oh + (((size_t)b * TT + qi0 + warp * 16) * NH + h) * HD;
    float inv0 = 1.0f / l_i[0];
    float inv1 = 1.0f / l_i[1];
#pragma unroll
    for (int nt = 0; nt < 16; nt++) {
        __half2 v0 = __floats2half2_rn(o[nt][0] * inv0, o[nt][1] * inv0);
        __half2 v1 = __floats2half2_rn(o[nt][2] * inv1, o[nt][3] * inv1);
        *(__half2*)&obase[(size_t)gid * QN + nt * 8 + 2 * tig]       = v0;
        *(__half2*)&obase[(size_t)(gid + 8) * QN + nt * 8 + 2 * tig] = v1;
    }
}

// ---------------------------------------------------------------------------
// Launch
// ---------------------------------------------------------------------------
extern "C" void kernel_launch(void* const* d_in, const int* in_sizes, int n_in,
                              void* d_out, int out_size)
{
    const float* x    = (const float*)d_in[0];
    const float* wq   = (const float*)d_in[1];
    const float* wk   = (const float*)d_in[2];
    const float* wv   = (const float*)d_in[3];
    const float* wo   = (const float*)d_in[4];
    const float* cosp = (const float*)d_in[5];
    const float* sinp = (const float*)d_in[6];
    float* out = (float*)d_out;

    float *qp, *kp, *vp;
    __half *qh, *kh, *ah, *xh, *wqT, *wkT, *wvT, *woT, *vt;
    cudaGetSymbolAddress((void**)&qp,  g_q);
    cudaGetSymbolAddress((void**)&kp,  g_k);
    cudaGetSymbolAddress((void**)&vp,  g_v);
    cudaGetSymbolAddress((void**)&qh,  g_qh);
    cudaGetSymbolAddress((void**)&kh,  g_kh);
    cudaGetSymbolAddress((void**)&ah,  g_ah);
    cudaGetSymbolAddress((void**)&xh,  g_xh);
    cudaGetSymbolAddress((void**)&wqT, g_wqT);
    cudaGetSymbolAddress((void**)&wkT, g_wkT);
    cudaGetSymbolAddress((void**)&wvT, g_wvT);
    cudaGetSymbolAddress((void**)&woT, g_woT);
    cudaGetSymbolAddress((void**)&vt,  g_vt);

    cudaFuncSetAttribute(attn_mma_kernel,
                         cudaFuncAttributeMaxDynamicSharedMemorySize,
                         ATTN_SMEM_BYTES);

    const float scale = 0.08838834764831845f;  // 1/sqrt(128)
    const int KW = DM / 2;                      // K in half2 words

    // x -> fp16 once
    {
        int n4 = MTOT * DM / 4;
        cvt_fp16_kernel<<<(n4 + 255) / 256, 256>>>(
            (const float4*)x, (uint2*)xh, n4);
    }

    // Transpose+convert weights to [N][K] fp16
    dim3 tb(32, 8);
    transpose_kernel<<<dim3(QN / 32, DM / 32), tb>>>(wq, wqT, DM, QN);
    transpose_kernel<<<dim3(KN / 32, DM / 32), tb>>>(wk, wkT, DM, KN);
    transpose_kernel<<<dim3(KN / 32, DM / 32), tb>>>(wv, wvT, DM, KN);
    transpose_kernel<<<dim3(QN / 32, DM / 32), tb>>>(wo, woT, DM, DM);

    // QKV projections (fp16 tensor cores, fp32 out)
    gemm_h<<<dim3(QN / GBN, MTOT / GBM), 256>>>(
        (const uint32_t*)xh, (const uint32_t*)wqT, qp, MTOT, QN, KW);
    gemm_h_kv<<<dim3(KN / GBN, MTOT / GBM, 2), 256>>>(
        (const uint32_t*)xh, (const uint32_t*)wkT, (const uint32_t*)wvT,
        kp, vp, MTOT, KN, KW);

    // RoPE fp32 -> fp16 (Q gets 1/sqrt(d) folded in)
    {
        int tq = BB * TT * NH * HALF;
        rope_h_kernel<<<(tq + 255) / 256, 256>>>(qp, qh, cosp, sinp, NH, scale);
        int tk = BB * TT * NKV * HALF;
        rope_h_kernel<<<(tk + 255) / 256, 256>>>(kp, kh, cosp, sinp, NKV, 1.0f);
    }

    // V -> fp16 transposed (b,kv,d,t)
    v_to_half_t_kernel<<<dim3(TT / 32, HD / 32, BB * NKV), tb>>>(vp, vt);

    // Flash attention (fp16 tensor cores)
    attn_mma_kernel<<<dim3(TT / 128, NH, BB), 256, ATTN_SMEM_BYTES>>>(
        qh, kh, vt, ah);

    // Output projection (fp16 tensor cores, fp32 out)
    gemm_h<<<dim3(QN / GBN, MTOT / GBM), 256>>>(
        (const uint32_t*)ah, (const uint32_t*)woT, out, MTOT, QN, KW);
}

// round 15
// speedup vs baseline: 5.8258x; 1.0000x over previous
#include <cuda_runtime.h>
#include <cuda_fp16.h>
#include <math.h>
#include <stdint.h>

// Problem constants
#define BB 2
#define TT 2048
#define DM 2048
#define NH 16
#define HD 128
#define NKV 4
#define NREP 4
#define HALF 64
#define MTOT (BB*TT)      // 4096
#define QN (NH*HD)        // 2048
#define KN (NKV*HD)       // 512

// Scratch (device globals: no allocations allowed)
__device__ float  g_q[MTOT * QN];      // 32 MB  Q proj out (fp32)
__device__ float  g_k[MTOT * KN];      //  8 MB  K proj out (fp32)
__device__ float  g_v[MTOT * KN];      //  8 MB  V proj out (fp32)
__device__ __half g_qh[MTOT * QN];     // 16 MB  rope(Q) fp16
__device__ __half g_kh[MTOT * KN];     //  4 MB  rope(K) fp16
__device__ __half g_ah[MTOT * QN];     // 16 MB  attention out fp16
__device__ __half g_xh[MTOT * DM];     // 16 MB  x as fp16
__device__ __half g_wqT[DM * QN];      //  8 MB  transposed fp16 weights [N][K]
__device__ __half g_wkT[DM * KN];      //  2 MB
__device__ __half g_wvT[DM * KN];      //  2 MB
__device__ __half g_woT[DM * DM];      //  8 MB
__device__ __half g_vt[(size_t)BB * NKV * HD * TT];  // 4 MB V^T fp16 (b,kv,d,t)

// ---------------------------------------------------------------------------
// MMA helpers (fp16, f32 accumulate)
// ---------------------------------------------------------------------------
__device__ __forceinline__ void mma_fp16(float* d, const uint32_t* a,
                                         uint32_t b0, uint32_t b1) {
    asm volatile(
        "mma.sync.aligned.m16n8k16.row.col.f32.f16.f16.f32 "
        "{%0,%1,%2,%3}, {%4,%5,%6,%7}, {%8,%9}, {%0,%1,%2,%3};\n"
        : "+f"(d[0]), "+f"(d[1]), "+f"(d[2]), "+f"(d[3])
        : "r"(a[0]), "r"(a[1]), "r"(a[2]), "r"(a[3]),
          "r"(b0), "r"(b1));
}

// ---------------------------------------------------------------------------
// Elementwise fp32 -> fp16
// ---------------------------------------------------------------------------
__global__ void cvt_fp16_kernel(const float4* __restrict__ src,
                                uint2* __restrict__ dst, int n4)
{
    int i = blockIdx.x * blockDim.x + threadIdx.x;
    if (i >= n4) return;
    float4 v = src[i];
    __half2 lo = __floats2half2_rn(v.x, v.y);
    __half2 hi = __floats2half2_rn(v.z, v.w);
    dst[i] = make_uint2(*(uint32_t*)&lo, *(uint32_t*)&hi);
}

// ---------------------------------------------------------------------------
// Weight transpose + fp16 convert: src [R][C] fp32 -> dst [C][R] fp16
// ---------------------------------------------------------------------------
__global__ void transpose_kernel(const float* __restrict__ src,
                                 __half* __restrict__ dst, int R, int C)
{
    __shared__ float t[32][33];
    int c0 = blockIdx.x * 32, r0 = blockIdx.y * 32;
    int x = threadIdx.x, y = threadIdx.y;   // block (32, 8)
#pragma unroll
    for (int i = 0; i < 32; i += 8)
        t[y + i][x] = src[(size_t)(r0 + y + i) * C + c0 + x];
    __syncthreads();
#pragma unroll
    for (int i = 0; i < 32; i += 8)
        dst[(size_t)(c0 + y + i) * R + r0 + x] = __float2half(t[x][y + i]);
}

// ---------------------------------------------------------------------------
// V fp32 (b,t,kv,d) -> V^T fp16 (b,kv,d,t)
// ---------------------------------------------------------------------------
__global__ void v_to_half_t_kernel(const float* __restrict__ v,
                                   __half* __restrict__ vt)
{
    __shared__ float t[32][33];
    int t0 = blockIdx.x * 32;
    int d0 = blockIdx.y * 32;
    int bk = blockIdx.z;
    int b = bk >> 2, kv = bk & 3;
    int x = threadIdx.x, y = threadIdx.y;   // (32, 8)
    const float* src = v + ((size_t)b * TT) * KN + kv * HD;
#pragma unroll
    for (int i = 0; i < 32; i += 8)
        t[y + i][x] = src[(size_t)(t0 + y + i) * KN + d0 + x];
    __syncthreads();
    __half* dst = vt + ((size_t)bk * HD + d0) * TT + t0;
#pragma unroll
    for (int i = 0; i < 32; i += 8)
        dst[(size_t)(y + i) * TT + x] = __float2half(t[x][y + i]);
}

// ---------------------------------------------------------------------------
// FP16 tensor-core GEMM: C[M,N] = A[M,K] @ B[K,N], fp32 out.
// A and Bt supplied as fp16 viewed as half2 WORDS; Kw = K/2 is the word count.
// Word-level fragment layout of m16n8k16.f16 == m16n8k8.tf32, so this is the
// validated R8 body with the MMA swapped. CTA tile 256x128 (elements),
// chunk = 16 words = 32 k-elements, 8 warps (4x2), warp tile 64x64.
// ---------------------------------------------------------------------------
#define GBM 256
#define GBN 128
#define GBKW 16   // words per chunk (= 32 halves)

__device__ __forceinline__ void gemm_body(
    const uint32_t* __restrict__ A, const uint32_t* __restrict__ Bt,
    float* __restrict__ C, int M, int N, int Kw)
{
    __shared__ __align__(16) uint32_t As[GBM * GBKW];
    __shared__ __align__(16) uint32_t Bs[GBN * GBKW];

    const int tid  = threadIdx.x;
    const int lane = tid & 31;
    const int warp = tid >> 5;
    const int gid  = lane >> 2;
    const int tig  = lane & 3;
    const int wy   = warp >> 1;
    const int wx   = warp & 1;
    const int m0   = blockIdx.y * GBM;
    const int n0   = blockIdx.x * GBN;

    const int c4    = tid & 3;
    const int rbase = tid >> 2;
    const int ksS   = c4 >> 1;
    const int khS   = c4 & 1;

    const uint32_t* Ag = A  + (size_t)(m0 + rbase) * Kw + c4 * 4;
    const uint32_t* Bg = Bt + (size_t)(n0 + rbase) * Kw + c4 * 4;

    float acc[4][8][4];
#pragma unroll
    for (int mt = 0; mt < 4; mt++)
#pragma unroll
        for (int nt = 0; nt < 8; nt++)
#pragma unroll
            for (int r = 0; r < 4; r++) acc[mt][nt][r] = 0.0f;

    uint4 pa[4], pb[2];
    const int NC = Kw / GBKW;

#pragma unroll
    for (int i = 0; i < 4; i++)
        pa[i] = *(const uint4*)&Ag[(size_t)(64 * i) * Kw];
#pragma unroll
    for (int i = 0; i < 2; i++)
        pb[i] = *(const uint4*)&Bg[(size_t)(64 * i) * Kw];

    {
#pragma unroll
        for (int i = 0; i < 4; i++) {
            int r  = rbase + 64 * i;
            int Mi = r >> 4, g = r & 7, rh = (r >> 3) & 1;
            int base = ((Mi * 2 + ksS) * 32 + g * 4);
            int roff = rh + 2 * khS;
            uint32_t e[4] = {pa[i].x, pa[i].y, pa[i].z, pa[i].w};
#pragma unroll
            for (int jj = 0; jj < 4; jj++) {
                int j = (jj + c4 + g) & 3;
                As[(base + j) * 4 + roff] = e[j];
            }
        }
#pragma unroll
        for (int i = 0; i < 2; i++) {
            int r  = rbase + 64 * i;
            int Ni = r >> 3, g = r & 7;
            int base = ((Ni * 2 + ksS) * 32 + g * 4);
            uint32_t e[4] = {pb[i].x, pb[i].y, pb[i].z, pb[i].w};
#pragma unroll
            for (int jj = 0; jj < 4; jj++) {
                int j = (jj + c4 + g) & 3;
                Bs[(base + j) * 2 + khS] = e[j];
            }
        }
    }
    __syncthreads();

    for (int kc = 0; kc < NC; kc++) {
        if (kc + 1 < NC) {
            size_t koff = (size_t)(kc + 1) * GBKW;
#pragma unroll
            for (int i = 0; i < 4; i++)
                pa[i] = *(const uint4*)&Ag[(size_t)(64 * i) * Kw + koff];
#pragma unroll
            for (int i = 0; i < 2; i++)
                pb[i] = *(const uint4*)&Bg[(size_t)(64 * i) * Kw + koff];
        }

#pragma unroll
        for (int ks = 0; ks < 2; ks++) {
            uint32_t a[4][4], b[8][2];
#pragma unroll
            for (int mt = 0; mt < 4; mt++) {
                int Mi = wy * 4 + mt;
                uint4 v = *(const uint4*)&As[((Mi * 2 + ks) * 32 + lane) * 4];
                a[mt][0] = v.x; a[mt][1] = v.y; a[mt][2] = v.z; a[mt][3] = v.w;
            }
#pragma unroll
            for (int nt = 0; nt < 8; nt++) {
                int Ni = wx * 8 + nt;
                uint2 v = *(const uint2*)&Bs[((Ni * 2 + ks) * 32 + lane) * 2];
                b[nt][0] = v.x; b[nt][1] = v.y;
            }
#pragma unroll
            for (int mt = 0; mt < 4; mt++)
#pragma unroll
                for (int nt = 0; nt < 8; nt++)
                    mma_fp16(acc[mt][nt], a[mt], b[nt][0], b[nt][1]);
        }

        if (kc + 1 < NC) {
            __syncthreads();
#pragma unroll
            for (int i = 0; i < 4; i++) {
                int r  = rbase + 64 * i;
                int Mi = r >> 4, g = r & 7, rh = (r >> 3) & 1;
                int base = ((Mi * 2 + ksS) * 32 + g * 4);
                int roff = rh + 2 * khS;
                uint32_t e[4] = {pa[i].x, pa[i].y, pa[i].z, pa[i].w};
#pragma unroll
                for (int jj = 0; jj < 4; jj++) {
                    int j = (jj + c4 + g) & 3;
                    As[(base + j) * 4 + roff] = e[j];
                }
            }
#pragma unroll
            for (int i = 0; i < 2; i++) {
                int r  = rbase + 64 * i;
                int Ni = r >> 3, g = r & 7;
                int base = ((Ni * 2 + ksS) * 32 + g * 4);
                uint32_t e[4] = {pb[i].x, pb[i].y, pb[i].z, pb[i].w};
#pragma unroll
                for (int jj = 0; jj < 4; jj++) {
                    int j = (jj + c4 + g) & 3;
                    Bs[(base + j) * 2 + khS] = e[j];
                }
            }
            __syncthreads();
        }
    }

#pragma unroll
    for (int mt = 0; mt < 4; mt++) {
        int row = m0 + wy * 64 + mt * 16 + gid;
#pragma unroll
        for (int nt = 0; nt < 8; nt++) {
            int col = n0 + wx * 64 + nt * 8 + tig * 2;
            float2 lo = {acc[mt][nt][0], acc[mt][nt][1]};
            float2 hi = {acc[mt][nt][2], acc[mt][nt][3]};
            *(float2*)&C[(size_t)row * N + col]       = lo;
            *(float2*)&C[(size_t)(row + 8) * N + col] = hi;
        }
    }
}

__global__ __launch_bounds__(256, 1) void gemm_h(
    const uint32_t* __restrict__ A, const uint32_t* __restrict__ Bt,
    float* __restrict__ C, int M, int N, int Kw)
{
    gemm_body(A, Bt, C, M, N, Kw);
}

__global__ __launch_bounds__(256, 1) void gemm_h_kv(
    const uint32_t* __restrict__ A,
    const uint32_t* __restrict__ BtK, const uint32_t* __restrict__ BtV,
    float* __restrict__ Ck, float* __restrict__ Cv, int M, int N, int Kw)
{
    const uint32_t* Bt = blockIdx.z ? BtV : BtK;
    float* C = blockIdx.z ? Cv : Ck;
    gemm_body(A, Bt, C, M, N, Kw);
}

// ---------------------------------------------------------------------------
// RoPE: read fp32 (b,t,heads,HD), rotate, scale, write fp16.
// ---------------------------------------------------------------------------
__global__ void rope_h_kernel(const float* __restrict__ q,
                              __half* __restrict__ qh,
                              const float* __restrict__ cosp,
                              const float* __restrict__ sinp,
                              int heads, float sc)
{
    int idx = blockIdx.x * blockDim.x + threadIdx.x;
    int total = BB * TT * heads * HALF;
    if (idx >= total) return;
    int i = idx % HALF;
    int h = (idx / HALF) % heads;
    int t = (idx / (HALF * heads)) % TT;
    int b = idx / (HALF * heads * TT);
    float c = cosp[t * HALF + i];
    float s = sinp[t * HALF + i];
    size_t base = (((size_t)b * TT + t) * heads + h) * HD;
    float x1 = q[base + i];
    float x2 = q[base + i + HALF];
    qh[base + i]        = __float2half((x1 * c - x2 * s) * sc);
    qh[base + i + HALF] = __float2half((x2 * c + x1 * s) * sc);
}

// ---------------------------------------------------------------------------
// FP16 tensor-core causal GQA flash attention.
// S = QK^T via m16n8k16.f16 (Q pre-scaled), softmax in registers,
// P in registers as fp16 A-frags, O += P@V via m16n8k16.f16.
// CTA: 128 q rows, key tiles of 64, 8 warps, warp owns 16 rows.
// Smem (words): Qs[128][68] half2, Ks[64][68] half2, Vw[128][36] half2.
// ---------------------------------------------------------------------------
#define AQS 68
#define AVS 36
#define ATTN_SMEM_BYTES ((128*AQS + 64*AQS + 128*AVS) * 4)   // 70656

__global__ __launch_bounds__(256, 1) void attn_mma_kernel(
    const __half* __restrict__ Qh, const __half* __restrict__ Kh,
    const __half* __restrict__ Vt, __half* __restrict__ Oh)
{
    extern __shared__ uint32_t smw[];
    uint32_t* Qs = smw;                  // [128][68] half2 words
    uint32_t* Ks = Qs + 128 * AQS;       // [64][68]
    uint32_t* Vw = Ks + 64 * AQS;        // [128][36] (V^T key-pairs)

    const int tid  = threadIdx.x;
    const int lane = tid & 31;
    const int warp = tid >> 5;
    const int gid  = lane >> 2;
    const int tig  = lane & 3;
    const int qt   = (gridDim.x - 1) - blockIdx.x;   // long CTAs first
    const int h    = blockIdx.y;
    const int b    = blockIdx.z;
    const int kvh  = h >> 2;
    const int qi0  = qt * 128;

    // ---- stage Q (half2 word copy; already scaled) ----
    const uint32_t* qbase = (const uint32_t*)Qh
        + (((size_t)b * TT + qi0) * NH + h) * (HD / 2);
#pragma unroll
    for (int i = 0; i < 8; i++) {
        int idx = tid + i * 256;        // 0..2047
        int r = idx >> 4, d4 = idx & 15;
        *(uint4*)&Qs[r * AQS + d4 * 4] =
            *(const uint4*)&qbase[(size_t)r * (QN / 2) + d4 * 4];
    }

    float m_i[2] = {-1e30f, -1e30f};
    float l_i[2] = {0.0f, 0.0f};
    float o[16][4];
#pragma unroll
    for (int nt = 0; nt < 16; nt++)
#pragma unroll
        for (int r = 0; r < 4; r++) o[nt][r] = 0.0f;

    const int arow = warp * 16 + gid;
    const int ntiles = qi0 / 64 + 2;
    const __half* vth = Vt + ((size_t)(b * NKV + kvh) * HD) * TT;

    for (int kt = 0; kt < ntiles; kt++) {
        const int kj0 = kt * 64;
        __syncthreads();

        // ---- stage K (half2 word copy) ----
        const uint32_t* kbase = (const uint32_t*)Kh
            + (((size_t)b * TT + kj0) * NKV + kvh) * (HD / 2);
#pragma unroll
        for (int i = 0; i < 4; i++) {
            int idx = tid + i * 256;    // 0..1023
            int r = idx >> 4, d4 = idx & 15;
            *(uint4*)&Ks[r * AQS + d4 * 4] =
                *(const uint4*)&kbase[(size_t)r * (KN / 2) + d4 * 4];
        }
        // ---- stage V^T (half2 copy) ----
#pragma unroll
        for (int i = 0; i < 16; i++) {
            int idx = i * 256 + tid;
            int kp = idx & 31, d = idx >> 5;
            Vw[d * AVS + kp] =
                *(const uint32_t*)&vth[(size_t)d * TT + kj0 + 2 * kp];
        }
        __syncthreads();

        // ---- S = Q K^T (fp16 mma, warp tile 16x64, 8 k16-steps) ----
        float s[8][4];
#pragma unroll
        for (int nt = 0; nt < 8; nt++)
#pragma unroll
            for (int r = 0; r < 4; r++) s[nt][r] = 0.0f;

#pragma unroll
        for (int ks = 0; ks < 8; ks++) {
            uint32_t a[4];
            int ab = arow * AQS + ks * 8 + tig;
            a[0] = Qs[ab];
            a[1] = Qs[ab + 8 * AQS];
            a[2] = Qs[ab + 4];
            a[3] = Qs[ab + 8 * AQS + 4];
#pragma unroll
            for (int nt = 0; nt < 8; nt++) {
                int kb = (nt * 8 + gid) * AQS + ks * 8 + tig;
                mma_fp16(s[nt], a, Ks[kb], Ks[kb + 4]);
            }
        }

        // ---- causal mask ----
        if (kt >= ntiles - 2) {
#pragma unroll
            for (int nt = 0; nt < 8; nt++)
#pragma unroll
                for (int r = 0; r < 4; r++) {
                    int row = qi0 + warp * 16 + gid + (r >> 1) * 8;
                    int col = kj0 + nt * 8 + 2 * tig + (r & 1);
                    if (col > row) s[nt][r] = -1e30f;
                }
        }

        // ---- online softmax ----
        uint32_t ph[8][2];
#pragma unroll
        for (int e = 0; e < 2; e++) {
            float mx = -1e30f;
#pragma unroll
            for (int nt = 0; nt < 8; nt++)
                mx = fmaxf(mx, fmaxf(s[nt][2 * e], s[nt][2 * e + 1]));
            mx = fmaxf(mx, __shfl_xor_sync(0xffffffffu, mx, 1));
            mx = fmaxf(mx, __shfl_xor_sync(0xffffffffu, mx, 2));
            float mnew = fmaxf(m_i[e], mx);
            float corr = __expf(m_i[e] - mnew);
            m_i[e] = mnew;
            float rsum = 0.0f;
#pragma unroll
            for (int nt = 0; nt < 8; nt++) {
                float p0 = __expf(s[nt][2 * e]     - mnew);
                float p1 = __expf(s[nt][2 * e + 1] - mnew);
                rsum += p0 + p1;
                __half2 hp = __floats2half2_rn(p0, p1);
                ph[nt][e] = *(uint32_t*)&hp;
            }
            rsum += __shfl_xor_sync(0xffffffffu, rsum, 1);
            rsum += __shfl_xor_sync(0xffffffffu, rsum, 2);
            l_i[e] = l_i[e] * corr + rsum;
#pragma unroll
            for (int nt = 0; nt < 16; nt++) {
                o[nt][2 * e]     *= corr;
                o[nt][2 * e + 1] *= corr;
            }
        }

        // ---- O += P @ V (fp16 mma) ----
#pragma unroll
        for (int ks = 0; ks < 4; ks++) {
            uint32_t a[4] = { ph[2 * ks][0], ph[2 * ks][1],
                              ph[2 * ks + 1][0], ph[2 * ks + 1][1] };
#pragma unroll
            for (int nt = 0; nt < 16; nt++) {
                int vb = (nt * 8 + gid) * AVS + ks * 8 + tig;
                mma_fp16(o[nt], a, Vw[vb], Vw[vb + 4]);
            }
        }
    }

    // ---- epilogue: normalize, write fp16 (feeds O-proj GEMM) ----
    __half* obase = Oh + (((size_t)b * TT + qi0 + warp * 16) * NH + h) * HD;
    float inv0 = 1.0f / l_i[0];
    float inv1 = 1.0f / l_i[1];
#pragma unroll
    for (int nt = 0; nt < 16; nt++) {
        __half2 v0 = __floats2half2_rn(o[nt][0] * inv0, o[nt][1] * inv0);
        __half2 v1 = __floats2half2_rn(o[nt][2] * inv1, o[nt][3] * inv1);
        *(__half2*)&obase[(size_t)gid * QN + nt * 8 + 2 * tig]       = v0;
        *(__half2*)&obase[(size_t)(gid + 8) * QN + nt * 8 + 2 * tig] = v1;
    }
}

// ---------------------------------------------------------------------------
// Launch
// ---------------------------------------------------------------------------
extern "C" void kernel_launch(void* const* d_in, const int* in_sizes, int n_in,
                              void* d_out, int out_size)
{
    const float* x    = (const float*)d_in[0];
    const float* wq   = (const float*)d_in[1];
    const float* wk   = (const float*)d_in[2];
    const float* wv   = (const float*)d_in[3];
    const float* wo   = (const float*)d_in[4];
    const float* cosp = (const float*)d_in[5];
    const float* sinp = (const float*)d_in[6];
    float* out = (float*)d_out;

    float *qp, *kp, *vp;
    __half *qh, *kh, *ah, *xh, *wqT, *wkT, *wvT, *woT, *vt;
    cudaGetSymbolAddress((void**)&qp,  g_q);
    cudaGetSymbolAddress((void**)&kp,  g_k);
    cudaGetSymbolAddress((void**)&vp,  g_v);
    cudaGetSymbolAddress((void**)&qh,  g_qh);
    cudaGetSymbolAddress((void**)&kh,  g_kh);
    cudaGetSymbolAddress((void**)&ah,  g_ah);
    cudaGetSymbolAddress((void**)&xh,  g_xh);
    cudaGetSymbolAddress((void**)&wqT, g_wqT);
    cudaGetSymbolAddress((void**)&wkT, g_wkT);
    cudaGetSymbolAddress((void**)&wvT, g_wvT);
    cudaGetSymbolAddress((void**)&woT, g_woT);
    cudaGetSymbolAddress((void**)&vt,  g_vt);

    cudaFuncSetAttribute(attn_mma_kernel,
                         cudaFuncAttributeMaxDynamicSharedMemorySize,
                         ATTN_SMEM_BYTES);

    const float scale = 0.08838834764831845f;  // 1/sqrt(128)
    const int KW = DM / 2;                      // K in half2 words

    // x -> fp16 once
    {
        int n4 = MTOT * DM / 4;
        cvt_fp16_kernel<<<(n4 + 255) / 256, 256>>>(
            (const float4*)x, (uint2*)xh, n4);
    }

    // Transpose+convert weights to [N][K] fp16
    dim3 tb(32, 8);
    transpose_kernel<<<dim3(QN / 32, DM / 32), tb>>>(wq, wqT, DM, QN);
    transpose_kernel<<<dim3(KN / 32, DM / 32), tb>>>(wk, wkT, DM, KN);
    transpose_kernel<<<dim3(KN / 32, DM / 32), tb>>>(wv, wvT, DM, KN);
    transpose_kernel<<<dim3(QN / 32, DM / 32), tb>>>(wo, woT, DM, DM);

    // QKV projections (fp16 tensor cores, fp32 out)
    gemm_h<<<dim3(QN / GBN, MTOT / GBM), 256>>>(
        (const uint32_t*)xh, (const uint32_t*)wqT, qp, MTOT, QN, KW);
    gemm_h_kv<<<dim3(KN / GBN, MTOT / GBM, 2), 256>>>(
        (const uint32_t*)xh, (const uint32_t*)wkT, (const uint32_t*)wvT,
        kp, vp, MTOT, KN, KW);

    // RoPE fp32 -> fp16 (Q gets 1/sqrt(d) folded in)
    {
        int tq = BB * TT * NH * HALF;
        rope_h_kernel<<<(tq + 255) / 256, 256>>>(qp, qh, cosp, sinp, NH, scale);
        int tk = BB * TT * NKV * HALF;
        rope_h_kernel<<<(tk + 255) / 256, 256>>>(kp, kh, cosp, sinp, NKV, 1.0f);
    }

    // V -> fp16 transposed (b,kv,d,t)
    v_to_half_t_kernel<<<dim3(TT / 32, HD / 32, BB * NKV), tb>>>(vp, vt);

    // Flash attention (fp16 tensor cores)
    attn_mma_kernel<<<dim3(TT / 128, NH, BB), 256, ATTN_SMEM_BYTES>>>(
        qh, kh, vt, ah);

    // Output projection (fp16 tensor cores, fp32 out)
    gemm_h<<<dim3(QN / GBN, MTOT / GBM), 256>>>(
        (const uint32_t*)ah, (const uint32_t*)woT, out, MTOT, QN, KW);
}